// round 8
// baseline (speedup 1.0000x reference)
#include <cuda_runtime.h>
#include <cuda_fp16.h>
#include <cstdint>

// Problem constants
#define BB 2
#define LL 2048
#define KK 2048
#define DD 512
#define HH 8
#define HD 64
#define RR 8
#define WWIN 8
#define EE (LL*WWIN)          // 16384 edges per batch
#define EH 16
#define TT 2
#define NLAM (HH*RR*HD)       // 4096
#define SCAP 256              // survivor cap in score kernel
#define LAMP 4112             // padded halves per edge chunk in iter2 smem (4096+16)

// ---------------- scratch (allocation-free: static device globals) ----------------
__device__ float  g_u [BB*HH*LL*HD];          // [B,H,L,HD]
__device__ float  g_v [BB*HH*KK*HD];          // [B,H,K,HD]
__device__ float  g_SA[BB*LL*EH];
__device__ float  g_SB[BB*KK*EH];
__device__ __half g_SBh[BB*KK*EH];            // fp16 copy for approx scoring
__device__ float  g_AA[BB*LL*EH];
__device__ float  g_AB[BB*KK*EH];
__device__ float  g_LA[BB*LL*EH];
__device__ float  g_LB[BB*KK*EH];
__device__ int    g_idx[BB*LL*WWIN];
__device__ __half g_Wl2h[NLAM*EH];            // Wl2 transposed [n][k] fp16

// ---------------- helpers ----------------
__device__ __forceinline__ float geluf(float x){
    return 0.5f * x * (1.0f + erff(x * 0.7071067811865475244f));
}
__device__ __forceinline__ float softplusf(float x){
    return (x > 20.f) ? x : log1pf(expf(x));
}
__device__ __forceinline__ float tf32_rna(float x){
    uint32_t u;
    asm("cvt.rna.tf32.f32 %0, %1;" : "=r"(u) : "f"(x));
    return __uint_as_float(u);
}
__device__ __forceinline__ unsigned flipf(float s){
    unsigned u = __float_as_uint(s);
    return (u & 0x80000000u) ? ~u : (u | 0x80000000u);
}
__device__ __forceinline__ __half2 tanh2(__half2 x){
    uint32_t r, a = *(uint32_t*)&x;
    asm("tanh.approx.f16x2 %0, %1;" : "=r"(r) : "r"(a));
    return *(__half2*)&r;
}
__device__ __forceinline__ void mma_tf32(float* d, const uint32_t* a, const uint32_t* b){
    asm("mma.sync.aligned.m16n8k8.row.col.f32.tf32.tf32.f32 "
        "{%0,%1,%2,%3}, {%4,%5,%6,%7}, {%8,%9}, {%0,%1,%2,%3};"
        : "+f"(d[0]), "+f"(d[1]), "+f"(d[2]), "+f"(d[3])
        : "r"(a[0]), "r"(a[1]), "r"(a[2]), "r"(a[3]), "r"(b[0]), "r"(b[1]));
}
__device__ __forceinline__ void mma_f16(float* d, uint32_t a0, uint32_t a1, uint32_t a2,
                                        uint32_t a3, uint32_t b0, uint32_t b1){
    asm("mma.sync.aligned.m16n8k16.row.col.f32.f16.f16.f32 "
        "{%0,%1,%2,%3}, {%4,%5,%6,%7}, {%8,%9}, {%0,%1,%2,%3};"
        : "+f"(d[0]), "+f"(d[1]), "+f"(d[2]), "+f"(d[3])
        : "r"(a0), "r"(a1), "r"(a2), "r"(a3), "r"(b0), "r"(b1));
}
__device__ __forceinline__ unsigned long long warp_max_ull(unsigned long long v){
#pragma unroll
    for (int o = 16; o; o >>= 1) {
        unsigned long long w = __shfl_xor_sync(0xffffffffu, v, o);
        if (w > v) v = w;
    }
    return v;
}
__device__ __forceinline__ float warp_fmax(float v){
#pragma unroll
    for (int o = 16; o; o >>= 1)
        v = fmaxf(v, __shfl_xor_sync(0xffffffffu, v, o));
    return v;
}

// ---------------- tf32 tensor-core GEMM: C = A[MxK] @ W[KxN] + bias ----------------
__global__ __launch_bounds__(256) void gemm32_kernel(
    const float* A, const float* W, const float* bias, float* C,
    int M, int N, int Kd, int aload, int smode,
    const float* A2, const float* W2, const float* bias2, float* C2, int halfM)
{
    __shared__ float As[128][36];
    __shared__ float Bs[32][72];
    int bm = blockIdx.y * 128;
    const int bn = blockIdx.x * 64;
    if (halfM && bm >= halfM) { A = A2; W = W2; bias = bias2; C = C2; bm -= halfM; }
    const int tid  = threadIdx.x;
    const int warp = tid >> 5, lane = tid & 31;
    const int wm = warp & 3, wn = warp >> 2;
    const int q = lane >> 2, c = lane & 3;

    float d[2][4][4];
#pragma unroll
    for (int mt = 0; mt < 2; mt++)
#pragma unroll
        for (int nt = 0; nt < 4; nt++)
#pragma unroll
            for (int i = 0; i < 4; i++) d[mt][nt][i] = 0.f;

    for (int k0 = 0; k0 < Kd; k0 += 32) {
#pragma unroll
        for (int i = 0; i < 4; i++) {
            int id = tid + i * 256;
            int m = id >> 3, kq = (id & 7) * 4;
            float4 v;
            if (aload) {
                int mm = bm + m; int b = mm >> 11, l = mm & 2047;
                int k = k0 + kq; int h = k >> 6, hd = k & 63;
                v = *(const float4*)&A[(((size_t)b * HH + h) * LL + l) * HD + hd];
            } else {
                v = *(const float4*)&A[(size_t)(bm + m) * Kd + k0 + kq];
            }
            float4 t = make_float4(tf32_rna(v.x), tf32_rna(v.y), tf32_rna(v.z), tf32_rna(v.w));
            *(float4*)&As[m][kq] = t;
        }
#pragma unroll
        for (int i = 0; i < 2; i++) {
            int id = tid + i * 256;
            int kk = id >> 4, nq = (id & 15) * 4;
            float4 v = *(const float4*)&W[(size_t)(k0 + kk) * N + bn + nq];
            float4 t = make_float4(tf32_rna(v.x), tf32_rna(v.y), tf32_rna(v.z), tf32_rna(v.w));
            *(float4*)&Bs[kk][nq] = t;
        }
        __syncthreads();
#pragma unroll
        for (int k8 = 0; k8 < 4; k8++) {
            uint32_t a[2][4], b[4][2];
#pragma unroll
            for (int mt = 0; mt < 2; mt++) {
                int r0 = wm * 32 + mt * 16 + q;
                a[mt][0] = __float_as_uint(As[r0    ][k8 * 8 + c]);
                a[mt][1] = __float_as_uint(As[r0 + 8][k8 * 8 + c]);
                a[mt][2] = __float_as_uint(As[r0    ][k8 * 8 + c + 4]);
                a[mt][3] = __float_as_uint(As[r0 + 8][k8 * 8 + c + 4]);
            }
#pragma unroll
            for (int nt = 0; nt < 4; nt++) {
                int cn = wn * 32 + nt * 8 + q;
                b[nt][0] = __float_as_uint(Bs[k8 * 8 + c    ][cn]);
                b[nt][1] = __float_as_uint(Bs[k8 * 8 + c + 4][cn]);
            }
#pragma unroll
            for (int mt = 0; mt < 2; mt++)
#pragma unroll
                for (int nt = 0; nt < 4; nt++)
                    mma_tf32(d[mt][nt], a[mt], b[nt]);
        }
        __syncthreads();
    }

#pragma unroll
    for (int mt = 0; mt < 2; mt++) {
        int gm0 = bm + wm * 32 + mt * 16 + q;
#pragma unroll
        for (int nt = 0; nt < 4; nt++) {
            int gn = bn + wn * 32 + nt * 8 + 2 * c;
            float b0 = __ldg(&bias[gn]), b1 = __ldg(&bias[gn + 1]);
            float v0 = d[mt][nt][0] + b0, v1 = d[mt][nt][1] + b1;
            float v2 = d[mt][nt][2] + b0, v3 = d[mt][nt][3] + b1;
            if (smode == 1) {
                int bb = gm0 >> 11, l = gm0 & 2047, h = gn >> 6, hd = gn & 63;
                float* p0 = &C[(((size_t)bb * HH + h) * LL + l) * HD + hd];
                p0[0] = v0; p0[1] = v1;
                float* p2 = &C[(((size_t)bb * HH + h) * LL + (l + 8)) * HD + hd];
                p2[0] = v2; p2[1] = v3;
            } else {
                *(float2*)&C[(size_t)gm0 * N + gn] = make_float2(v0, v1);
                *(float2*)&C[(size_t)(gm0 + 8) * N + gn] = make_float2(v2, v3);
            }
        }
    }
}

// ---------------- Wl2 transpose+convert: [16][4096] f32 -> [4096][16] f16 ----------
__global__ void prep_wl2_kernel(const float* __restrict__ Wl2)
{
    int n = blockIdx.x * blockDim.x + threadIdx.x;
    if (n >= NLAM) return;
#pragma unroll
    for (int k = 0; k < EH; k++)
        g_Wl2h[n * EH + k] = __float2half(Wl2[(size_t)k * NLAM + n]);
}

// ---------------- 512->48 projection (both inputs), 12 cols/thread ----------------
__global__ __launch_bounds__(128) void proj_kernel(
    const float* __restrict__ Xt, const float* __restrict__ Xc,
    const float* __restrict__ W1, const float* __restrict__ W2, const float* __restrict__ W3,
    float* __restrict__ O1t, float* __restrict__ O2t, float* __restrict__ O3t,
    float* __restrict__ O1c, float* __restrict__ O2c, float* __restrict__ O3c)
{
    __shared__ float Xs[32][68];
    __shared__ float Ws[64][52];
    const int grow0 = blockIdx.x * 32;
    const int sel = grow0 >= (BB * LL);
    const float* X = sel ? Xc : Xt;
    const int row0 = grow0 & (BB * LL - 1);
    const int koff = sel ? DD : 0;
    const int tid = threadIdx.x;
    const int r = tid >> 2, c0 = (tid & 3) * 12;

    float acc[12];
#pragma unroll
    for (int j = 0; j < 12; j++) acc[j] = 0.f;

    for (int k0 = 0; k0 < DD; k0 += 64) {
#pragma unroll
        for (int i = 0; i < 4; i++) {
            int id = tid + i * 128;
            int rr = id >> 4, qq = (id & 15) * 4;
            *(float4*)&Xs[rr][qq] = *(const float4*)&X[(size_t)(row0 + rr) * DD + k0 + qq];
        }
#pragma unroll
        for (int i = 0; i < 2; i++) {
            int id = tid + i * 128;
            int kr = id >> 2, qq = (id & 3) * 4;
            *(float4*)&Ws[kr][ 0 + qq] = *(const float4*)&W1[(size_t)(koff + k0 + kr) * EH + qq];
            *(float4*)&Ws[kr][16 + qq] = *(const float4*)&W2[(size_t)(koff + k0 + kr) * EH + qq];
            *(float4*)&Ws[kr][32 + qq] = *(const float4*)&W3[(size_t)(koff + k0 + kr) * EH + qq];
        }
        __syncthreads();
#pragma unroll
        for (int k = 0; k < 64; k++) {
            float x = Xs[r][k];
            float4 w0 = *(const float4*)&Ws[k][c0];
            float4 w1 = *(const float4*)&Ws[k][c0 + 4];
            float4 w2 = *(const float4*)&Ws[k][c0 + 8];
            acc[0] += x * w0.x;  acc[1] += x * w0.y;  acc[2]  += x * w0.z;  acc[3]  += x * w0.w;
            acc[4] += x * w1.x;  acc[5] += x * w1.y;  acc[6]  += x * w1.z;  acc[7]  += x * w1.w;
            acc[8] += x * w2.x;  acc[9] += x * w2.y;  acc[10] += x * w2.z;  acc[11] += x * w2.w;
        }
        __syncthreads();
    }

    const int row = row0 + r;
#pragma unroll
    for (int j = 0; j < 12; j++) {
        int cc = c0 + j;
        int m = cc >> 4, col = cc & 15;
        float* O = sel ? (m == 0 ? O1c : m == 1 ? O2c : O3c)
                       : (m == 0 ? O1t : m == 1 ? O2t : O3t);
        O[(size_t)row * EH + col] = acc[j];
        if (sel && m == 0)
            g_SBh[(size_t)row * EH + col] = __float2half(acc[j]);
    }
}

// ---------------- score + top-8: sigmoid-gelu approx, float threshold, exact rescue
__global__ __launch_bounds__(256) void score_topk_kernel(
    const float* __restrict__ bs1, const float* __restrict__ Ws2, const float* __restrict__ bs2)
{
    __shared__ float a16[EH];
    __shared__ float w2s[EH];
    __shared__ __half2 a2h[8];
    __shared__ __half2 w2h[8];
    __shared__ float s_wv[8][8];
    __shared__ unsigned long long s_wk[8][8];
    __shared__ int s_surv[SCAP];
    __shared__ int s_cnt;
    __shared__ float s_thr;

    int b = blockIdx.x >> 11, l = blockIdx.x & 2047;
    int tid = threadIdx.x;
    int warp = tid >> 5, lane = tid & 31;
    if (tid < EH) {
        a16[tid] = g_SA[((size_t)b * LL + l) * EH + tid] + bs1[tid];
        w2s[tid] = Ws2[tid];
    }
    __syncthreads();
    if (tid < 8) {
        a2h[tid] = __floats2half2_rn(a16[2 * tid], a16[2 * tid + 1]);
        w2h[tid] = __floats2half2_rn(w2s[2 * tid], w2s[2 * tid + 1]);
    }
    __syncthreads();
    float aR[EH], wR[EH];
#pragma unroll
    for (int c = 0; c < EH; c++) { aR[c] = a16[c]; wR[c] = w2s[c]; }
    __half2 aH[8], wH[8];
#pragma unroll
    for (int c = 0; c < 8; c++) { aH[c] = a2h[c]; wH[c] = w2h[c]; }
    float bs2v = bs2[0];
    const __half2 C851 = __float2half2_rn(0.851f);   // 1.702/2 (tanh form of sigmoid)
    const __half2 H5 = __float2half2_rn(0.5f);
    const float NINF = __int_as_float(0xff800000);

    // phase A: sigmoid-gelu (5 half2 ops/channel), per-thread fp32 max only
    float s8[8];
    float tmax = NINF;
#pragma unroll
    for (int i = 0; i < 8; i++) {
        int kk = tid + i * 256;
        const uint4* bp = (const uint4*)(g_SBh + ((size_t)b * KK + kk) * EH);
        uint4 r0 = bp[0], r1 = bp[1];
        uint32_t bw[8] = {r0.x, r0.y, r0.z, r0.w, r1.x, r1.y, r1.z, r1.w};
        __half2 acc = __float2half2_rn(0.f);
#pragma unroll
        for (int c = 0; c < 8; c++) {
            __half2 h  = __hadd2(aH[c], *(__half2*)&bw[c]);
            __half2 t  = __hmul2(h, C851);
            __half2 th = tanh2(t);
            __half2 hh = __hmul2(h, H5);
            __half2 rs = __hfma2(hh, th, hh);
            acc = __hfma2(rs, wH[c], acc);
        }
        float2 f = __half22float2(acc);
        float s = f.x + f.y + bs2v;
        s8[i] = s;
        tmax = fmaxf(tmax, s);
    }

    // warp top-8 over 32 thread-maxes (fp32 fmax + shuffle)
    {
        float v = tmax;
#pragma unroll
        for (int p = 0; p < 8; p++) {
            float best = warp_fmax(v);
            if (v == best) v = NINF;
            if (lane == 0) s_wv[warp][p] = best;
        }
    }
    __syncthreads();

    // warp 0: merge 64 -> t8' and threshold (2B margin for sigmoid-gelu + fp16)
    if (warp == 0) {
        float va = ((float*)s_wv)[lane];
        float vb = ((float*)s_wv)[lane + 32];
        float t8 = NINF;
#pragma unroll
        for (int p = 0; p < 8; p++) {
            float m = fmaxf(va, vb);
            float best = warp_fmax(m);
            if (va == best) va = NINF; else if (vb == best) vb = NINF;
            t8 = best;
        }
        if (lane == 0) {
            float sw = 0.f;
#pragma unroll
            for (int c = 0; c < EH; c++) sw += fabsf(w2s[c]);
            s_thr = t8 - (sw * 0.08f + 0.12f);
            s_cnt = 0;
        }
    }
    __syncthreads();

    // survivor scan from register scores
    float thr = s_thr;
#pragma unroll
    for (int i = 0; i < 8; i++) {
        if (s8[i] >= thr) {
            int p = atomicAdd(&s_cnt, 1);
            if (p < SCAP) s_surv[p] = tid + i * 256;
        }
    }
    __syncthreads();
    int n = s_cnt;
    bool fb = (n > SCAP);

    unsigned long long key = 0ull;
    if (!fb) {
        if (tid < n) {
            int kk = s_surv[tid];
            const float4* bp = (const float4*)(g_SB + ((size_t)b * KK + kk) * EH);
            float4 b0 = bp[0], b1 = bp[1], b2 = bp[2], b3 = bp[3];
            float bv[EH] = {b0.x,b0.y,b0.z,b0.w, b1.x,b1.y,b1.z,b1.w,
                            b2.x,b2.y,b2.z,b2.w, b3.x,b3.y,b3.z,b3.w};
            float s = bs2v;
#pragma unroll
            for (int c = 0; c < EH; c++) s += geluf(aR[c] + bv[c]) * wR[c];
            key = (((unsigned long long)flipf(s)) << 32) | (unsigned)(KK - 1 - kk);
        }
#pragma unroll
        for (int p = 0; p < 8; p++) {
            unsigned long long best = warp_max_ull(key);
            if (key == best && best != 0ull) key = 0ull;
            if (lane == 0) s_wk[warp][p] = best;
        }
    } else {
        // fallback: exact rescore of everything (rare)
        unsigned long long k8[8];
#pragma unroll
        for (int i = 0; i < 8; i++) {
            int kk = tid + i * 256;
            const float4* bp = (const float4*)(g_SB + ((size_t)b * KK + kk) * EH);
            float4 b0 = bp[0], b1 = bp[1], b2 = bp[2], b3 = bp[3];
            float bv[EH] = {b0.x,b0.y,b0.z,b0.w, b1.x,b1.y,b1.z,b1.w,
                            b2.x,b2.y,b2.z,b2.w, b3.x,b3.y,b3.z,b3.w};
            float s = bs2v;
#pragma unroll
            for (int c = 0; c < EH; c++) s += geluf(aR[c] + bv[c]) * wR[c];
            k8[i] = (((unsigned long long)flipf(s)) << 32) | (unsigned)(KK - 1 - kk);
        }
        unsigned long long lm = k8[0]; int am = 0;
#pragma unroll
        for (int i = 1; i < 8; i++) if (k8[i] > lm) { lm = k8[i]; am = i; }
#pragma unroll
        for (int p = 0; p < 8; p++) {
            unsigned long long best = warp_max_ull(lm);
            if (lm == best && best != 0ull) {
                k8[am] = 0ull;
                lm = k8[0]; am = 0;
#pragma unroll
                for (int i = 1; i < 8; i++) if (k8[i] > lm) { lm = k8[i]; am = i; }
            }
            if (lane == 0) s_wk[warp][p] = best;
        }
    }
    __syncthreads();

    if (warp == 0) {
        unsigned long long ka = ((unsigned long long*)s_wk)[lane];
        unsigned long long kb = ((unsigned long long*)s_wk)[lane + 32];
#pragma unroll
        for (int p = 0; p < 8; p++) {
            unsigned long long m = ka > kb ? ka : kb;
            unsigned long long best = warp_max_ull(m);
            if (ka == best) ka = 0ull; else if (kb == best) kb = 0ull;
            if (lane == 0)
                g_idx[((size_t)b * LL + l) * WWIN + p] = KK - 1 - (int)(best & 0xffffffffu);
        }
    }
}

// ---------------- fused consensus, 512 threads: 2 warps per head ------------------
// Warp w: head h = w>>1, partition p = w&1 (edges p*4+eg). Lam generation and the
// iteration loop are split across the warp pair; residuals combine via 4KB smem.
// Both warps of a pair replay identical fp32 u-updates -> bitwise-consistent state.
#define ITER_DYN_SMEM (8*LAMP*2 + 8*HH*HD*4 + 16*8*8*4)   // 65792+16384+4096 = 86272
__global__ __launch_bounds__(512) void iter2_kernel(
    const float* __restrict__ step_sizes, const float* __restrict__ bl1,
    const float* __restrict__ ba1, const float* __restrict__ Wa2,
    const float* __restrict__ ba2, const float* __restrict__ bl2)
{
    extern __shared__ char dyn[];
    __half* s_lam = (__half*)dyn;                        // [8e] x LAMP halves
    float*  s_v   = (float*)(dyn + 8*LAMP*2);            // [8e][H][64]
    float*  s_red = (float*)(dyn + 8*LAMP*2 + 8*HH*HD*4);// [16w][8dg][8]
    __shared__ float s_cs[8][32];
    __shared__ float s_sn[8][32];
    __shared__ float s_alpha[8];
    __shared__ int   s_idx[8];
    __shared__ __half s_gh[8][EH];

    int b = blockIdx.x >> 11, l = blockIdx.x & 2047;
    int tid = threadIdx.x;
    int wi = tid >> 5, ln = tid & 31;
    int h = wi >> 1, p = wi & 1;
    int eg = ln >> 3, dg = ln & 7;
    int q = ln >> 2, cq = ln & 3;

    // per-edge small params: warps 0..7 own edge e = wi
    if (wi < 8) {
        int e = wi;
        int j = g_idx[((size_t)b * LL + l) * WWIN + e];
        if (ln == 0) s_idx[e] = j;
        float hav = 0.f;
        if (ln < EH) {
            int c = ln;
            float hl = g_LA[((size_t)b * LL + l) * EH + c]
                     + g_LB[((size_t)b * KK + j) * EH + c] + bl1[c];
            s_gh[e][c] = __float2half(geluf(hl));
            float ha = g_AA[((size_t)b * LL + l) * EH + c]
                     + g_AB[((size_t)b * KK + j) * EH + c] + ba1[c];
            hav = geluf(ha) * Wa2[c];
        }
#pragma unroll
        for (int o = 16; o; o >>= 1) hav += __shfl_xor_sync(0xffffffffu, hav, o);
        if (ln == 0) s_alpha[e] = softplusf(hav + ba2[0]);
        float ang = (float)(l - j) * exp2f((float)ln * -0.41524101186092029f);
        s_cs[e][ln] = cosf(ang);
        s_sn[e][ln] = sinf(ang);
    }
    __syncthreads();

    // stage gathered v rows (512 threads, 8 each)
#pragma unroll
    for (int i = 0; i < 8; i++) {
        int gid = tid + i * 512;
        int e2 = gid >> 9, h2 = (gid >> 6) & 7, d = gid & 63;
        s_v[gid] = g_v[(((size_t)b * HH + h2) * KK + s_idx[e2]) * HD + d];
    }

    // generate Lam: warp covers 256 cols of head h (half p), rows = edges
    {
        uint32_t A0 = *(const uint32_t*)&s_gh[q][2 * cq];
        uint32_t A2 = *(const uint32_t*)&s_gh[q][2 * cq + 8];
        uint32_t Z = 0u;
        const int cbase = h * 512 + p * 256;
#pragma unroll
        for (int rr = 0; rr < 4; rr++) {
            float v0a[8], v1a[8];
            float ssq = 0.f;
#pragma unroll
            for (int ii = 0; ii < 8; ii++) {
                int colq = cbase + (rr * 8 + ii) * 8 + q;
                const uint32_t* bp = (const uint32_t*)(g_Wl2h + (size_t)colq * EH);
                uint32_t b0 = bp[cq], b1 = bp[cq + 4];
                float dd[4] = {0.f, 0.f, 0.f, 0.f};
                mma_f16(dd, A0, Z, A2, Z, b0, b1);
                int ncol = cbase + (rr * 8 + ii) * 8 + 2 * cq;
                float2 bb = *(const float2*)&bl2[ncol];
                v0a[ii] = dd[0] + bb.x;
                v1a[ii] = dd[1] + bb.y;
                ssq += v0a[ii] * v0a[ii] + v1a[ii] * v1a[ii];
            }
            ssq += __shfl_xor_sync(0xffffffffu, ssq, 1);
            ssq += __shfl_xor_sync(0xffffffffu, ssq, 2);
            float sc = 1.f / fmaxf(sqrtf(ssq), 1e-12f);
#pragma unroll
            for (int ii = 0; ii < 8; ii++) {
                int ncol = cbase + (rr * 8 + ii) * 8 + 2 * cq;
                *(__half2*)&s_lam[(size_t)q * LAMP + ncol] =
                    __floats2half2_rn(v0a[ii] * sc, v1a[ii] * sc);
            }
        }
    }
    __syncthreads();

    size_t ubase = (((size_t)b * HH + h) * LL + l) * HD;
    float4 u_lo = *(const float4*)&g_u[ubase + dg * 4];
    float4 u_hi = *(const float4*)&g_u[ubase + 32 + dg * 4];

#pragma unroll
    for (int t = 0; t < TT; t++) {
        float stp = softplusf(step_sizes[t * LL + l]);
        float al4[4] = {0.f,0.f,0.f,0.f}, ah4[4] = {0.f,0.f,0.f,0.f};
        {
            int e = p * 4 + eg;
            float4 cs4 = *(const float4*)&s_cs[e][dg * 4];
            float4 sn4 = *(const float4*)&s_sn[e][dg * 4];
            const float4* vp = (const float4*)&s_v[(e * HH + h) * HD + dg * 4];
            float4 vlo = vp[0], vhi = vp[8];
            float dlo[4], dhi[4];
            dlo[0] = u_lo.x * cs4.x - u_hi.x * sn4.x - vlo.x;
            dlo[1] = u_lo.y * cs4.y - u_hi.y * sn4.y - vlo.y;
            dlo[2] = u_lo.z * cs4.z - u_hi.z * sn4.z - vlo.z;
            dlo[3] = u_lo.w * cs4.w - u_hi.w * sn4.w - vlo.w;
            dhi[0] = u_hi.x * cs4.x + u_lo.x * sn4.x - vhi.x;
            dhi[1] = u_hi.y * cs4.y + u_lo.y * sn4.y - vhi.y;
            dhi[2] = u_hi.z * cs4.z + u_lo.z * sn4.z - vhi.z;
            dhi[3] = u_hi.w * cs4.w + u_lo.w * sn4.w - vhi.w;
            float alp = s_alpha[e];
            float rl[4] = {0.f,0.f,0.f,0.f}, rh[4] = {0.f,0.f,0.f,0.f};
            const __half2* lp = (const __half2*)(s_lam + (size_t)e * LAMP + h * RR * HD);
#pragma unroll
            for (int r = 0; r < RR; r++) {
                __half2 hl0 = lp[r * 32 + dg * 2], hl1 = lp[r * 32 + dg * 2 + 1];
                __half2 hh0 = lp[r * 32 + 16 + dg * 2], hh1 = lp[r * 32 + 16 + dg * 2 + 1];
                float2 f0 = __half22float2(hl0), f1 = __half22float2(hl1);
                float2 f2 = __half22float2(hh0), f3 = __half22float2(hh1);
                float pr = f0.x * dlo[0] + f0.y * dlo[1] + f1.x * dlo[2] + f1.y * dlo[3]
                         + f2.x * dhi[0] + f2.y * dhi[1] + f3.x * dhi[2] + f3.y * dhi[3];
                pr += __shfl_xor_sync(0xffffffffu, pr, 1);
                pr += __shfl_xor_sync(0xffffffffu, pr, 2);
                pr += __shfl_xor_sync(0xffffffffu, pr, 4);
                rl[0] += pr * f0.x; rl[1] += pr * f0.y; rl[2] += pr * f1.x; rl[3] += pr * f1.y;
                rh[0] += pr * f2.x; rh[1] += pr * f2.y; rh[2] += pr * f3.x; rh[3] += pr * f3.y;
            }
#pragma unroll
            for (int i = 0; i < 4; i++) {
                al4[i] = alp * dlo[i] + rl[i];
                ah4[i] = alp * dhi[i] + rh[i];
            }
        }
        // combine the 4 edge-groups within the warp (lanes differing in bits 3,4)
#pragma unroll
        for (int i = 0; i < 4; i++) {
            al4[i] += __shfl_xor_sync(0xffffffffu, al4[i], 8);
            al4[i] += __shfl_xor_sync(0xffffffffu, al4[i], 16);
            ah4[i] += __shfl_xor_sync(0xffffffffu, ah4[i], 8);
            ah4[i] += __shfl_xor_sync(0xffffffffu, ah4[i], 16);
        }
        // cross-warp (edge halves) combine via smem
        if (eg == 0) {
            float* rp = &s_red[(wi * 8 + dg) * 8];
            *(float4*)&rp[0] = make_float4(al4[0], al4[1], al4[2], al4[3]);
            *(float4*)&rp[4] = make_float4(ah4[0], ah4[1], ah4[2], ah4[3]);
        }
        __syncthreads();
        {
            const float* rp = &s_red[((wi ^ 1) * 8 + dg) * 8];
            float4 oa = *(const float4*)&rp[0];
            float4 ob = *(const float4*)&rp[4];
            al4[0] += oa.x; al4[1] += oa.y; al4[2] += oa.z; al4[3] += oa.w;
            ah4[0] += ob.x; ah4[1] += ob.y; ah4[2] += ob.z; ah4[3] += ob.w;
        }
        u_lo.x -= stp * al4[0]; u_lo.y -= stp * al4[1];
        u_lo.z -= stp * al4[2]; u_lo.w -= stp * al4[3];
        u_hi.x -= stp * ah4[0]; u_hi.y -= stp * ah4[1];
        u_hi.z -= stp * ah4[2]; u_hi.w -= stp * ah4[3];
        __syncthreads();   // s_red write-after-read guard for next iteration
    }
    if (p == 0 && eg == 0) {
        *(float4*)&g_u[ubase + dg * 4] = u_lo;
        *(float4*)&g_u[ubase + 32 + dg * 4] = u_hi;
    }
}

// ---------------- launch ----------------
extern "C" void kernel_launch(void* const* d_in, const int* in_sizes, int n_in,
                              void* d_out, int out_size)
{
    const float* target = (const float*)d_in[0];
    const float* context= (const float*)d_in[1];
    const float* Wt  = (const float*)d_in[2];
    const float* bt  = (const float*)d_in[3];
    const float* Wc  = (const float*)d_in[4];
    const float* bc  = (const float*)d_in[5];
    const float* Ws1 = (const float*)d_in[6];
    const float* bs1 = (const float*)d_in[7];
    const float* Ws2 = (const float*)d_in[8];
    const float* bs2 = (const float*)d_in[9];
    const float* Wa1 = (const float*)d_in[10];
    const float* ba1 = (const float*)d_in[11];
    const float* Wa2 = (const float*)d_in[12];
    const float* ba2 = (const float*)d_in[13];
    const float* Wl1 = (const float*)d_in[14];
    const float* bl1 = (const float*)d_in[15];
    const float* Wl2 = (const float*)d_in[16];
    const float* bl2 = (const float*)d_in[17];
    const float* step_sizes = (const float*)d_in[18];
    const float* Wo  = (const float*)d_in[19];
    const float* bo  = (const float*)d_in[20];

    float *pu, *pv, *pSA, *pSB, *pAA, *pAB, *pLA, *pLB;
    cudaGetSymbolAddress((void**)&pu,  g_u);
    cudaGetSymbolAddress((void**)&pv,  g_v);
    cudaGetSymbolAddress((void**)&pSA, g_SA);
    cudaGetSymbolAddress((void**)&pSB, g_SB);
    cudaGetSymbolAddress((void**)&pAA, g_AA);
    cudaGetSymbolAddress((void**)&pAB, g_AB);
    cudaGetSymbolAddress((void**)&pLA, g_LA);
    cudaGetSymbolAddress((void**)&pLB, g_LB);

    cudaFuncSetAttribute(iter2_kernel, cudaFuncAttributeMaxDynamicSharedMemorySize,
                         ITER_DYN_SMEM);

    const int Mrows = BB * LL;  // 4096

    // u and v projections in one launch
    gemm32_kernel<<<dim3(DD/64, (2*Mrows)/128), 256>>>(
        target, Wt, bt, pu, 2*Mrows, DD, DD, 0, 1, context, Wc, bc, pv, Mrows);

    prep_wl2_kernel<<<(NLAM + 255) / 256, 256>>>(Wl2);

    // separable 16-dim projections (fp32 exact + SB fp16 shadow)
    proj_kernel<<<(2*Mrows)/32, 128>>>(target, context, Ws1, Wa1, Wl1,
                                       pSA, pAA, pLA, pSB, pAB, pLB);

    // scores + top-8 (sigmoid-gelu approx, float threshold, exact rescue)
    score_topk_kernel<<<BB * LL, 256>>>(bs1, Ws2, bs2);

    // fused: edge params + in-block Lam generation + both consensus iterations
    iter2_kernel<<<BB * LL, 512, ITER_DYN_SMEM>>>(step_sizes, bl1, ba1, Wa2, ba2, bl2);

    gemm32_kernel<<<dim3(DD/64, Mrows/128), 256>>>(
        pu, Wo, bo, (float*)d_out, Mrows, DD, DD, 1, 0,
        nullptr, nullptr, nullptr, nullptr, 0);
}

// round 9
// speedup vs baseline: 1.0354x; 1.0354x over previous
#include <cuda_runtime.h>
#include <cuda_fp16.h>
#include <cstdint>

// Problem constants
#define BB 2
#define LL 2048
#define KK 2048
#define DD 512
#define HH 8
#define HD 64
#define RR 8
#define WWIN 8
#define EE (LL*WWIN)          // 16384 edges per batch
#define EH 16
#define TT 2
#define NLAM (HH*RR*HD)       // 4096
#define SCAP 256              // survivor cap in score kernel
#define LAMP 4112             // padded halves per edge chunk in iter2 smem (4096+16)

// ---------------- scratch (allocation-free: static device globals) ----------------
__device__ float  g_u [BB*HH*LL*HD];          // [B,H,L,HD]
__device__ float  g_v [BB*HH*KK*HD];          // [B,H,K,HD]
__device__ float  g_SA[BB*LL*EH];
__device__ float  g_SB[BB*KK*EH];
__device__ __half g_SBh[BB*KK*EH];            // fp16 copy for approx scoring
__device__ float  g_AA[BB*LL*EH];
__device__ float  g_AB[BB*KK*EH];
__device__ float  g_LA[BB*LL*EH];
__device__ float  g_LB[BB*KK*EH];
__device__ int    g_idx[BB*LL*WWIN];
__device__ __half g_Wl2h[NLAM*EH];            // Wl2 transposed [n][k] fp16

// ---------------- helpers ----------------
__device__ __forceinline__ float geluf(float x){
    return 0.5f * x * (1.0f + erff(x * 0.7071067811865475244f));
}
__device__ __forceinline__ float softplusf(float x){
    return (x > 20.f) ? x : log1pf(expf(x));
}
__device__ __forceinline__ float tf32_rna(float x){
    uint32_t u;
    asm("cvt.rna.tf32.f32 %0, %1;" : "=r"(u) : "f"(x));
    return __uint_as_float(u);
}
__device__ __forceinline__ unsigned flipf(float s){
    unsigned u = __float_as_uint(s);
    return (u & 0x80000000u) ? ~u : (u | 0x80000000u);
}
__device__ __forceinline__ __half2 tanh2(__half2 x){
    uint32_t r, a = *(uint32_t*)&x;
    asm("tanh.approx.f16x2 %0, %1;" : "=r"(r) : "r"(a));
    return *(__half2*)&r;
}
__device__ __forceinline__ void mma_tf32(float* d, const uint32_t* a, const uint32_t* b){
    asm("mma.sync.aligned.m16n8k8.row.col.f32.tf32.tf32.f32 "
        "{%0,%1,%2,%3}, {%4,%5,%6,%7}, {%8,%9}, {%0,%1,%2,%3};"
        : "+f"(d[0]), "+f"(d[1]), "+f"(d[2]), "+f"(d[3])
        : "r"(a[0]), "r"(a[1]), "r"(a[2]), "r"(a[3]), "r"(b[0]), "r"(b[1]));
}
__device__ __forceinline__ void mma_f16(float* d, uint32_t a0, uint32_t a1, uint32_t a2,
                                        uint32_t a3, uint32_t b0, uint32_t b1){
    asm("mma.sync.aligned.m16n8k16.row.col.f32.f16.f16.f32 "
        "{%0,%1,%2,%3}, {%4,%5,%6,%7}, {%8,%9}, {%0,%1,%2,%3};"
        : "+f"(d[0]), "+f"(d[1]), "+f"(d[2]), "+f"(d[3])
        : "r"(a0), "r"(a1), "r"(a2), "r"(a3), "r"(b0), "r"(b1));
}
__device__ __forceinline__ unsigned long long warp_max_ull(unsigned long long v){
#pragma unroll
    for (int o = 16; o; o >>= 1) {
        unsigned long long w = __shfl_xor_sync(0xffffffffu, v, o);
        if (w > v) v = w;
    }
    return v;
}
__device__ __forceinline__ float warp_fmax(float v){
#pragma unroll
    for (int o = 16; o; o >>= 1)
        v = fmaxf(v, __shfl_xor_sync(0xffffffffu, v, o));
    return v;
}

// ---------------- tf32 tensor-core GEMM: C = A[MxK] @ W[KxN] + bias ----------------
__global__ __launch_bounds__(256) void gemm32_kernel(
    const float* A, const float* W, const float* bias, float* C,
    int M, int N, int Kd, int aload, int smode,
    const float* A2, const float* W2, const float* bias2, float* C2, int halfM)
{
    __shared__ float As[128][36];
    __shared__ float Bs[32][72];
    int bm = blockIdx.y * 128;
    const int bn = blockIdx.x * 64;
    if (halfM && bm >= halfM) { A = A2; W = W2; bias = bias2; C = C2; bm -= halfM; }
    const int tid  = threadIdx.x;
    const int warp = tid >> 5, lane = tid & 31;
    const int wm = warp & 3, wn = warp >> 2;
    const int q = lane >> 2, c = lane & 3;

    float d[2][4][4];
#pragma unroll
    for (int mt = 0; mt < 2; mt++)
#pragma unroll
        for (int nt = 0; nt < 4; nt++)
#pragma unroll
            for (int i = 0; i < 4; i++) d[mt][nt][i] = 0.f;

    for (int k0 = 0; k0 < Kd; k0 += 32) {
#pragma unroll
        for (int i = 0; i < 4; i++) {
            int id = tid + i * 256;
            int m = id >> 3, kq = (id & 7) * 4;
            float4 v;
            if (aload) {
                int mm = bm + m; int b = mm >> 11, l = mm & 2047;
                int k = k0 + kq; int h = k >> 6, hd = k & 63;
                v = *(const float4*)&A[(((size_t)b * HH + h) * LL + l) * HD + hd];
            } else {
                v = *(const float4*)&A[(size_t)(bm + m) * Kd + k0 + kq];
            }
            float4 t = make_float4(tf32_rna(v.x), tf32_rna(v.y), tf32_rna(v.z), tf32_rna(v.w));
            *(float4*)&As[m][kq] = t;
        }
#pragma unroll
        for (int i = 0; i < 2; i++) {
            int id = tid + i * 256;
            int kk = id >> 4, nq = (id & 15) * 4;
            float4 v = *(const float4*)&W[(size_t)(k0 + kk) * N + bn + nq];
            float4 t = make_float4(tf32_rna(v.x), tf32_rna(v.y), tf32_rna(v.z), tf32_rna(v.w));
            *(float4*)&Bs[kk][nq] = t;
        }
        __syncthreads();
#pragma unroll
        for (int k8 = 0; k8 < 4; k8++) {
            uint32_t a[2][4], b[4][2];
#pragma unroll
            for (int mt = 0; mt < 2; mt++) {
                int r0 = wm * 32 + mt * 16 + q;
                a[mt][0] = __float_as_uint(As[r0    ][k8 * 8 + c]);
                a[mt][1] = __float_as_uint(As[r0 + 8][k8 * 8 + c]);
                a[mt][2] = __float_as_uint(As[r0    ][k8 * 8 + c + 4]);
                a[mt][3] = __float_as_uint(As[r0 + 8][k8 * 8 + c + 4]);
            }
#pragma unroll
            for (int nt = 0; nt < 4; nt++) {
                int cn = wn * 32 + nt * 8 + q;
                b[nt][0] = __float_as_uint(Bs[k8 * 8 + c    ][cn]);
                b[nt][1] = __float_as_uint(Bs[k8 * 8 + c + 4][cn]);
            }
#pragma unroll
            for (int mt = 0; mt < 2; mt++)
#pragma unroll
                for (int nt = 0; nt < 4; nt++)
                    mma_tf32(d[mt][nt], a[mt], b[nt]);
        }
        __syncthreads();
    }

#pragma unroll
    for (int mt = 0; mt < 2; mt++) {
        int gm0 = bm + wm * 32 + mt * 16 + q;
#pragma unroll
        for (int nt = 0; nt < 4; nt++) {
            int gn = bn + wn * 32 + nt * 8 + 2 * c;
            float b0 = __ldg(&bias[gn]), b1 = __ldg(&bias[gn + 1]);
            float v0 = d[mt][nt][0] + b0, v1 = d[mt][nt][1] + b1;
            float v2 = d[mt][nt][2] + b0, v3 = d[mt][nt][3] + b1;
            if (smode == 1) {
                int bb = gm0 >> 11, l = gm0 & 2047, h = gn >> 6, hd = gn & 63;
                float* p0 = &C[(((size_t)bb * HH + h) * LL + l) * HD + hd];
                p0[0] = v0; p0[1] = v1;
                float* p2 = &C[(((size_t)bb * HH + h) * LL + (l + 8)) * HD + hd];
                p2[0] = v2; p2[1] = v3;
            } else {
                *(float2*)&C[(size_t)gm0 * N + gn] = make_float2(v0, v1);
                *(float2*)&C[(size_t)(gm0 + 8) * N + gn] = make_float2(v2, v3);
            }
        }
    }
}

// ---------------- Wl2 transpose+convert: [16][4096] f32 -> [4096][16] f16 ----------
__global__ void prep_wl2_kernel(const float* __restrict__ Wl2)
{
    int n = blockIdx.x * blockDim.x + threadIdx.x;
    if (n >= NLAM) return;
#pragma unroll
    for (int k = 0; k < EH; k++)
        g_Wl2h[n * EH + k] = __float2half(Wl2[(size_t)k * NLAM + n]);
}

// ---------------- 512->48 projection (both inputs), 12 cols/thread ----------------
__global__ __launch_bounds__(128) void proj_kernel(
    const float* __restrict__ Xt, const float* __restrict__ Xc,
    const float* __restrict__ W1, const float* __restrict__ W2, const float* __restrict__ W3,
    float* __restrict__ O1t, float* __restrict__ O2t, float* __restrict__ O3t,
    float* __restrict__ O1c, float* __restrict__ O2c, float* __restrict__ O3c)
{
    __shared__ float Xs[32][68];
    __shared__ float Ws[64][52];
    const int grow0 = blockIdx.x * 32;
    const int sel = grow0 >= (BB * LL);
    const float* X = sel ? Xc : Xt;
    const int row0 = grow0 & (BB * LL - 1);
    const int koff = sel ? DD : 0;
    const int tid = threadIdx.x;
    const int r = tid >> 2, c0 = (tid & 3) * 12;

    float acc[12];
#pragma unroll
    for (int j = 0; j < 12; j++) acc[j] = 0.f;

    for (int k0 = 0; k0 < DD; k0 += 64) {
#pragma unroll
        for (int i = 0; i < 4; i++) {
            int id = tid + i * 128;
            int rr = id >> 4, qq = (id & 15) * 4;
            *(float4*)&Xs[rr][qq] = *(const float4*)&X[(size_t)(row0 + rr) * DD + k0 + qq];
        }
#pragma unroll
        for (int i = 0; i < 2; i++) {
            int id = tid + i * 128;
            int kr = id >> 2, qq = (id & 3) * 4;
            *(float4*)&Ws[kr][ 0 + qq] = *(const float4*)&W1[(size_t)(koff + k0 + kr) * EH + qq];
            *(float4*)&Ws[kr][16 + qq] = *(const float4*)&W2[(size_t)(koff + k0 + kr) * EH + qq];
            *(float4*)&Ws[kr][32 + qq] = *(const float4*)&W3[(size_t)(koff + k0 + kr) * EH + qq];
        }
        __syncthreads();
#pragma unroll
        for (int k = 0; k < 64; k++) {
            float x = Xs[r][k];
            float4 w0 = *(const float4*)&Ws[k][c0];
            float4 w1 = *(const float4*)&Ws[k][c0 + 4];
            float4 w2 = *(const float4*)&Ws[k][c0 + 8];
            acc[0] += x * w0.x;  acc[1] += x * w0.y;  acc[2]  += x * w0.z;  acc[3]  += x * w0.w;
            acc[4] += x * w1.x;  acc[5] += x * w1.y;  acc[6]  += x * w1.z;  acc[7]  += x * w1.w;
            acc[8] += x * w2.x;  acc[9] += x * w2.y;  acc[10] += x * w2.z;  acc[11] += x * w2.w;
        }
        __syncthreads();
    }

    const int row = row0 + r;
#pragma unroll
    for (int j = 0; j < 12; j++) {
        int cc = c0 + j;
        int m = cc >> 4, col = cc & 15;
        float* O = sel ? (m == 0 ? O1c : m == 1 ? O2c : O3c)
                       : (m == 0 ? O1t : m == 1 ? O2t : O3t);
        O[(size_t)row * EH + col] = acc[j];
        if (sel && m == 0)
            g_SBh[(size_t)row * EH + col] = __float2half(acc[j]);
    }
}

// ---------------- score + top-8: tanh-gelu approx, float threshold, exact rescue ---
__global__ __launch_bounds__(256) void score_topk_kernel(
    const float* __restrict__ bs1, const float* __restrict__ Ws2, const float* __restrict__ bs2)
{
    __shared__ float a16[EH];
    __shared__ float w2s[EH];
    __shared__ __half2 a2h[8];
    __shared__ __half2 w2h[8];
    __shared__ float s_wv[8][8];
    __shared__ unsigned long long s_wk[8][8];
    __shared__ int s_surv[SCAP];
    __shared__ int s_cnt;
    __shared__ float s_thr;

    int b = blockIdx.x >> 11, l = blockIdx.x & 2047;
    int tid = threadIdx.x;
    int warp = tid >> 5, lane = tid & 31;
    if (tid < EH) {
        a16[tid] = g_SA[((size_t)b * LL + l) * EH + tid] + bs1[tid];
        w2s[tid] = Ws2[tid];
    }
    __syncthreads();
    if (tid < 8) {
        a2h[tid] = __floats2half2_rn(a16[2 * tid], a16[2 * tid + 1]);
        w2h[tid] = __floats2half2_rn(w2s[2 * tid], w2s[2 * tid + 1]);
    }
    __syncthreads();
    float aR[EH], wR[EH];
#pragma unroll
    for (int c = 0; c < EH; c++) { aR[c] = a16[c]; wR[c] = w2s[c]; }
    __half2 aH[8], wH[8];
#pragma unroll
    for (int c = 0; c < 8; c++) { aH[c] = a2h[c]; wH[c] = w2h[c]; }
    float bs2v = bs2[0];
    const __half2 C1 = __float2half2_rn(0.0356774081f);   // 0.79788456*0.044715
    const __half2 C0 = __float2half2_rn(0.7978845608f);
    const __half2 H5 = __float2half2_rn(0.5f);
    const float NINF = __int_as_float(0xff800000);

    // phase A: half2 tanh-gelu scores, per-thread fp32 max only (no keys)
    float s8[8];
    float tmax = NINF;
#pragma unroll
    for (int i = 0; i < 8; i++) {
        int kk = tid + i * 256;
        const uint4* bp = (const uint4*)(g_SBh + ((size_t)b * KK + kk) * EH);
        uint4 r0 = bp[0], r1 = bp[1];
        uint32_t bw[8] = {r0.x, r0.y, r0.z, r0.w, r1.x, r1.y, r1.z, r1.w};
        __half2 acc = __float2half2_rn(0.f);
#pragma unroll
        for (int c = 0; c < 8; c++) {
            __half2 h  = __hadd2(aH[c], *(__half2*)&bw[c]);
            __half2 p  = __hmul2(h, h);
            __half2 qq = __hfma2(p, C1, C0);
            __half2 t  = __hmul2(h, qq);
            __half2 th = tanh2(t);
            __half2 hh = __hmul2(h, H5);
            __half2 rs = __hfma2(hh, th, hh);
            acc = __hfma2(rs, wH[c], acc);
        }
        float2 f = __half22float2(acc);
        float s = f.x + f.y + bs2v;
        s8[i] = s;
        tmax = fmaxf(tmax, s);
    }

    // warp top-8 over 32 thread-maxes (fp32 fmax + shuffle)
    {
        float v = tmax;
#pragma unroll
        for (int p = 0; p < 8; p++) {
            float best = warp_fmax(v);
            if (v == best) v = NINF;
            if (lane == 0) s_wv[warp][p] = best;
        }
    }
    __syncthreads();

    // warp 0: merge 64 -> t8' and threshold
    if (warp == 0) {
        float va = ((float*)s_wv)[lane];
        float vb = ((float*)s_wv)[lane + 32];
        float t8 = NINF;
#pragma unroll
        for (int p = 0; p < 8; p++) {
            float m = fmaxf(va, vb);
            float best = warp_fmax(m);
            if (va == best) va = NINF; else if (vb == best) vb = NINF;
            t8 = best;
        }
        if (lane == 0) {
            float sw = 0.f;
#pragma unroll
            for (int c = 0; c < EH; c++) sw += fabsf(w2s[c]);
            s_thr = t8 - (sw * 0.03f + 0.06f);
            s_cnt = 0;
        }
    }
    __syncthreads();

    // survivor scan from register scores
    float thr = s_thr;
#pragma unroll
    for (int i = 0; i < 8; i++) {
        if (s8[i] >= thr) {
            int p = atomicAdd(&s_cnt, 1);
            if (p < SCAP) s_surv[p] = tid + i * 256;
        }
    }
    __syncthreads();
    int n = s_cnt;
    bool fb = (n > SCAP);

    unsigned long long key = 0ull;
    if (!fb) {
        if (tid < n) {
            int kk = s_surv[tid];
            const float4* bp = (const float4*)(g_SB + ((size_t)b * KK + kk) * EH);
            float4 b0 = bp[0], b1 = bp[1], b2 = bp[2], b3 = bp[3];
            float bv[EH] = {b0.x,b0.y,b0.z,b0.w, b1.x,b1.y,b1.z,b1.w,
                            b2.x,b2.y,b2.z,b2.w, b3.x,b3.y,b3.z,b3.w};
            float s = bs2v;
#pragma unroll
            for (int c = 0; c < EH; c++) s += geluf(aR[c] + bv[c]) * wR[c];
            key = (((unsigned long long)flipf(s)) << 32) | (unsigned)(KK - 1 - kk);
        }
#pragma unroll
        for (int p = 0; p < 8; p++) {
            unsigned long long best = warp_max_ull(key);
            if (key == best && best != 0ull) key = 0ull;
            if (lane == 0) s_wk[warp][p] = best;
        }
    } else {
        // fallback: exact rescore of everything (rare)
        unsigned long long k8[8];
#pragma unroll
        for (int i = 0; i < 8; i++) {
            int kk = tid + i * 256;
            const float4* bp = (const float4*)(g_SB + ((size_t)b * KK + kk) * EH);
            float4 b0 = bp[0], b1 = bp[1], b2 = bp[2], b3 = bp[3];
            float bv[EH] = {b0.x,b0.y,b0.z,b0.w, b1.x,b1.y,b1.z,b1.w,
                            b2.x,b2.y,b2.z,b2.w, b3.x,b3.y,b3.z,b3.w};
            float s = bs2v;
#pragma unroll
            for (int c = 0; c < EH; c++) s += geluf(aR[c] + bv[c]) * wR[c];
            k8[i] = (((unsigned long long)flipf(s)) << 32) | (unsigned)(KK - 1 - kk);
        }
        unsigned long long lm = k8[0]; int am = 0;
#pragma unroll
        for (int i = 1; i < 8; i++) if (k8[i] > lm) { lm = k8[i]; am = i; }
#pragma unroll
        for (int p = 0; p < 8; p++) {
            unsigned long long best = warp_max_ull(lm);
            if (lm == best && best != 0ull) {
                k8[am] = 0ull;
                lm = k8[0]; am = 0;
#pragma unroll
                for (int i = 1; i < 8; i++) if (k8[i] > lm) { lm = k8[i]; am = i; }
            }
            if (lane == 0) s_wk[warp][p] = best;
        }
    }
    __syncthreads();

    if (warp == 0) {
        unsigned long long ka = ((unsigned long long*)s_wk)[lane];
        unsigned long long kb = ((unsigned long long*)s_wk)[lane + 32];
#pragma unroll
        for (int p = 0; p < 8; p++) {
            unsigned long long m = ka > kb ? ka : kb;
            unsigned long long best = warp_max_ull(m);
            if (ka == best) ka = 0ull; else if (kb == best) kb = 0ull;
            if (lane == 0)
                g_idx[((size_t)b * LL + l) * WWIN + p] = KK - 1 - (int)(best & 0xffffffffu);
        }
    }
}

// ---------------- fused consensus: gh/alpha + in-block Lam MMA + T=2 iterations ---
// r-loop restructured into chunks of 4: 4 independent dots, then 3 butterfly
// rounds over 4 p-values (breaks the serial 3-shfl-per-r dependency chain).
// FP expression and per-value reduction order identical to the serial version.
#define ITER_DYN_SMEM (8*LAMP*2 + 8*HH*HD*4)   // 65792 + 16384 = 82176 B
__global__ __launch_bounds__(256) void iter2_kernel(
    const float* __restrict__ step_sizes, const float* __restrict__ bl1,
    const float* __restrict__ ba1, const float* __restrict__ Wa2,
    const float* __restrict__ ba2, const float* __restrict__ bl2)
{
    extern __shared__ char dyn[];
    __half* s_lam = (__half*)dyn;                        // [8e] x LAMP halves
    float*  s_v   = (float*)(dyn + 8*LAMP*2);            // [8e][H][64]
    __shared__ float s_cs[8][32];
    __shared__ float s_sn[8][32];
    __shared__ float s_alpha[8];
    __shared__ int   s_idx[8];
    __shared__ __half s_gh[8][EH];

    int b = blockIdx.x >> 11, l = blockIdx.x & 2047;
    int tid = threadIdx.x;
    int wi = tid >> 5, ln = tid & 31;
    int eg = ln >> 3, dg = ln & 7;
    int q = ln >> 2, cq = ln & 3;

    // per-edge small params: warp e owns edge e
    {
        int e = wi;
        int j = g_idx[((size_t)b * LL + l) * WWIN + e];
        if (ln == 0) s_idx[e] = j;
        float hav = 0.f;
        if (ln < EH) {
            int c = ln;
            float hl = g_LA[((size_t)b * LL + l) * EH + c]
                     + g_LB[((size_t)b * KK + j) * EH + c] + bl1[c];
            s_gh[e][c] = __float2half(geluf(hl));
            float ha = g_AA[((size_t)b * LL + l) * EH + c]
                     + g_AB[((size_t)b * KK + j) * EH + c] + ba1[c];
            hav = geluf(ha) * Wa2[c];
        }
#pragma unroll
        for (int o = 16; o; o >>= 1) hav += __shfl_xor_sync(0xffffffffu, hav, o);
        if (ln == 0) s_alpha[e] = softplusf(hav + ba2[0]);
        float ang = (float)(l - j) * exp2f((float)ln * -0.41524101186092029f);
        s_cs[e][ln] = cosf(ang);
        s_sn[e][ln] = sinf(ang);
    }
    __syncthreads();

    // stage gathered v rows
#pragma unroll
    for (int i = 0; i < 16; i++) {
        int gid = tid + i * 256;
        int e2 = gid >> 9, h2 = (gid >> 6) & 7, d = gid & 63;
        s_v[gid] = g_v[(((size_t)b * HH + h2) * KK + s_idx[e2]) * HD + d];
    }

    // generate Lam for head wi: rows = edges (A rows 0-7 valid), 512 cols per warp
    {
        uint32_t A0 = *(const uint32_t*)&s_gh[q][2 * cq];
        uint32_t A2 = *(const uint32_t*)&s_gh[q][2 * cq + 8];
        uint32_t Z = 0u;
#pragma unroll
        for (int rr = 0; rr < 8; rr++) {
            float v0a[8], v1a[8];
            float ssq = 0.f;
#pragma unroll
            for (int ii = 0; ii < 8; ii++) {
                int colq = wi * 512 + (rr * 8 + ii) * 8 + q;       // B col this thread
                const uint32_t* bp = (const uint32_t*)(g_Wl2h + (size_t)colq * EH);
                uint32_t b0 = bp[cq], b1 = bp[cq + 4];
                float dd[4] = {0.f, 0.f, 0.f, 0.f};
                mma_f16(dd, A0, Z, A2, Z, b0, b1);
                int ncol = wi * 512 + (rr * 8 + ii) * 8 + 2 * cq;  // output cols (edge q)
                float2 bb = *(const float2*)&bl2[ncol];
                v0a[ii] = dd[0] + bb.x;
                v1a[ii] = dd[1] + bb.y;
                ssq += v0a[ii] * v0a[ii] + v1a[ii] * v1a[ii];
            }
            ssq += __shfl_xor_sync(0xffffffffu, ssq, 1);
            ssq += __shfl_xor_sync(0xffffffffu, ssq, 2);
            float sc = 1.f / fmaxf(sqrtf(ssq), 1e-12f);
#pragma unroll
            for (int ii = 0; ii < 8; ii++) {
                int ncol = wi * 512 + (rr * 8 + ii) * 8 + 2 * cq;
                *(__half2*)&s_lam[(size_t)q * LAMP + ncol] =
                    __floats2half2_rn(v0a[ii] * sc, v1a[ii] * sc);
            }
        }
    }
    __syncthreads();

    size_t ubase = (((size_t)b * HH + wi) * LL + l) * HD;
    float4 u_lo = *(const float4*)&g_u[ubase + dg * 4];
    float4 u_hi = *(const float4*)&g_u[ubase + 32 + dg * 4];

#pragma unroll
    for (int t = 0; t < TT; t++) {
        float stp = softplusf(step_sizes[t * LL + l]);
        float al4[4] = {0.f,0.f,0.f,0.f}, ah4[4] = {0.f,0.f,0.f,0.f};
#pragma unroll
        for (int eb = 0; eb < 2; eb++) {
            int e = eb * 4 + eg;
            float4 cs4 = *(const float4*)&s_cs[e][dg * 4];
            float4 sn4 = *(const float4*)&s_sn[e][dg * 4];
            const float4* vp = (const float4*)&s_v[(e * HH + wi) * HD + dg * 4];
            float4 vlo = vp[0], vhi = vp[8];
            float dlo[4], dhi[4];
            dlo[0] = u_lo.x * cs4.x - u_hi.x * sn4.x - vlo.x;
            dlo[1] = u_lo.y * cs4.y - u_hi.y * sn4.y - vlo.y;
            dlo[2] = u_lo.z * cs4.z - u_hi.z * sn4.z - vlo.z;
            dlo[3] = u_lo.w * cs4.w - u_hi.w * sn4.w - vlo.w;
            dhi[0] = u_hi.x * cs4.x + u_lo.x * sn4.x - vhi.x;
            dhi[1] = u_hi.y * cs4.y + u_lo.y * sn4.y - vhi.y;
            dhi[2] = u_hi.z * cs4.z + u_lo.z * sn4.z - vhi.z;
            dhi[3] = u_hi.w * cs4.w + u_lo.w * sn4.w - vhi.w;
            float alp = s_alpha[e];
            float rl[4] = {0.f,0.f,0.f,0.f}, rh[4] = {0.f,0.f,0.f,0.f};
            const __half2* lp = (const __half2*)(s_lam + (size_t)e * LAMP + wi * RR * HD);
#pragma unroll
            for (int rc = 0; rc < 2; rc++) {
                float2 F0[4], F1[4], F2[4], F3[4];
                float p4[4];
#pragma unroll
                for (int rr2 = 0; rr2 < 4; rr2++) {
                    int r = rc * 4 + rr2;
                    uint2 wlo = *(const uint2*)&lp[r * 32 + dg * 2];
                    uint2 whi = *(const uint2*)&lp[r * 32 + 16 + dg * 2];
                    F0[rr2] = __half22float2(*(__half2*)&wlo.x);
                    F1[rr2] = __half22float2(*(__half2*)&wlo.y);
                    F2[rr2] = __half22float2(*(__half2*)&whi.x);
                    F3[rr2] = __half22float2(*(__half2*)&whi.y);
                    p4[rr2] = F0[rr2].x * dlo[0] + F0[rr2].y * dlo[1]
                            + F1[rr2].x * dlo[2] + F1[rr2].y * dlo[3]
                            + F2[rr2].x * dhi[0] + F2[rr2].y * dhi[1]
                            + F3[rr2].x * dhi[2] + F3[rr2].y * dhi[3];
                }
                // butterfly all 4 p-values together: each round's shuffles independent
#pragma unroll
                for (int o = 1; o <= 4; o <<= 1) {
#pragma unroll
                    for (int rr2 = 0; rr2 < 4; rr2++)
                        p4[rr2] += __shfl_xor_sync(0xffffffffu, p4[rr2], o);
                }
#pragma unroll
                for (int rr2 = 0; rr2 < 4; rr2++) {
                    rl[0] += p4[rr2] * F0[rr2].x; rl[1] += p4[rr2] * F0[rr2].y;
                    rl[2] += p4[rr2] * F1[rr2].x; rl[3] += p4[rr2] * F1[rr2].y;
                    rh[0] += p4[rr2] * F2[rr2].x; rh[1] += p4[rr2] * F2[rr2].y;
                    rh[2] += p4[rr2] * F3[rr2].x; rh[3] += p4[rr2] * F3[rr2].y;
                }
            }
#pragma unroll
            for (int i = 0; i < 4; i++) {
                al4[i] += alp * dlo[i] + rl[i];
                ah4[i] += alp * dhi[i] + rh[i];
            }
        }
#pragma unroll
        for (int i = 0; i < 4; i++) {
            al4[i] += __shfl_xor_sync(0xffffffffu, al4[i], 8);
            al4[i] += __shfl_xor_sync(0xffffffffu, al4[i], 16);
            ah4[i] += __shfl_xor_sync(0xffffffffu, ah4[i], 8);
            ah4[i] += __shfl_xor_sync(0xffffffffu, ah4[i], 16);
        }
        u_lo.x -= stp * al4[0]; u_lo.y -= stp * al4[1];
        u_lo.z -= stp * al4[2]; u_lo.w -= stp * al4[3];
        u_hi.x -= stp * ah4[0]; u_hi.y -= stp * ah4[1];
        u_hi.z -= stp * ah4[2]; u_hi.w -= stp * ah4[3];
    }
    if (eg == 0) {
        *(float4*)&g_u[ubase + dg * 4] = u_lo;
        *(float4*)&g_u[ubase + 32 + dg * 4] = u_hi;
    }
}

// ---------------- launch ----------------
extern "C" void kernel_launch(void* const* d_in, const int* in_sizes, int n_in,
                              void* d_out, int out_size)
{
    const float* target = (const float*)d_in[0];
    const float* context= (const float*)d_in[1];
    const float* Wt  = (const float*)d_in[2];
    const float* bt  = (const float*)d_in[3];
    const float* Wc  = (const float*)d_in[4];
    const float* bc  = (const float*)d_in[5];
    const float* Ws1 = (const float*)d_in[6];
    const float* bs1 = (const float*)d_in[7];
    const float* Ws2 = (const float*)d_in[8];
    const float* bs2 = (const float*)d_in[9];
    const float* Wa1 = (const float*)d_in[10];
    const float* ba1 = (const float*)d_in[11];
    const float* Wa2 = (const float*)d_in[12];
    const float* ba2 = (const float*)d_in[13];
    const float* Wl1 = (const float*)d_in[14];
    const float* bl1 = (const float*)d_in[15];
    const float* Wl2 = (const float*)d_in[16];
    const float* bl2 = (const float*)d_in[17];
    const float* step_sizes = (const float*)d_in[18];
    const float* Wo  = (const float*)d_in[19];
    const float* bo  = (const float*)d_in[20];

    float *pu, *pv, *pSA, *pSB, *pAA, *pAB, *pLA, *pLB;
    cudaGetSymbolAddress((void**)&pu,  g_u);
    cudaGetSymbolAddress((void**)&pv,  g_v);
    cudaGetSymbolAddress((void**)&pSA, g_SA);
    cudaGetSymbolAddress((void**)&pSB, g_SB);
    cudaGetSymbolAddress((void**)&pAA, g_AA);
    cudaGetSymbolAddress((void**)&pAB, g_AB);
    cudaGetSymbolAddress((void**)&pLA, g_LA);
    cudaGetSymbolAddress((void**)&pLB, g_LB);

    cudaFuncSetAttribute(iter2_kernel, cudaFuncAttributeMaxDynamicSharedMemorySize,
                         ITER_DYN_SMEM);

    const int Mrows = BB * LL;  // 4096

    // u and v projections in one launch
    gemm32_kernel<<<dim3(DD/64, (2*Mrows)/128), 256>>>(
        target, Wt, bt, pu, 2*Mrows, DD, DD, 0, 1, context, Wc, bc, pv, Mrows);

    prep_wl2_kernel<<<(NLAM + 255) / 256, 256>>>(Wl2);

    // separable 16-dim projections (fp32 exact + SB fp16 shadow)
    proj_kernel<<<(2*Mrows)/32, 128>>>(target, context, Ws1, Wa1, Wl1,
                                       pSA, pAA, pLA, pSB, pAB, pLB);

    // scores + top-8 (tanh-gelu approx, float threshold, exact rescue)
    score_topk_kernel<<<BB * LL, 256>>>(bs1, Ws2, bs2);

    // fused: edge params + in-block Lam generation + both consensus iterations
    iter2_kernel<<<BB * LL, 256, ITER_DYN_SMEM>>>(step_sizes, bl1, ba1, Wa2, ba2, bl2);

    gemm32_kernel<<<dim3(DD/64, Mrows/128), 256>>>(
        pu, Wo, bo, (float*)d_out, Mrows, DD, DD, 1, 0,
        nullptr, nullptr, nullptr, nullptr, 0);
}

// round 10
// speedup vs baseline: 1.0692x; 1.0326x over previous
#include <cuda_runtime.h>
#include <cuda_fp16.h>
#include <cstdint>

// Problem constants
#define BB 2
#define LL 2048
#define KK 2048
#define DD 512
#define HH 8
#define HD 64
#define RR 8
#define WWIN 8
#define EE (LL*WWIN)          // 16384 edges per batch
#define EH 16
#define TT 2
#define NLAM (HH*RR*HD)       // 4096
#define SCAP 256              // survivor cap in score kernel
#define LAMP 4112             // padded halves per edge chunk in iter2 smem (4096+16)

// ---------------- scratch (allocation-free: static device globals) ----------------
__device__ float  g_u [BB*HH*LL*HD];          // [B,H,L,HD]
__device__ float  g_v [BB*HH*KK*HD];          // [B,H,K,HD]
__device__ float  g_SA[BB*LL*EH];
__device__ float  g_SB[BB*KK*EH];
__device__ __half g_SBh[BB*KK*EH];            // fp16 copy for approx scoring
__device__ float  g_AA[BB*LL*EH];
__device__ float  g_AB[BB*KK*EH];
__device__ float  g_LA[BB*LL*EH];
__device__ float  g_LB[BB*KK*EH];
__device__ int    g_idx[BB*LL*WWIN];
__device__ __half g_Wl2h[NLAM*EH];            // Wl2 transposed [n][k] fp16

// ---------------- helpers ----------------
__device__ __forceinline__ float geluf(float x){
    return 0.5f * x * (1.0f + erff(x * 0.7071067811865475244f));
}
__device__ __forceinline__ float softplusf(float x){
    return (x > 20.f) ? x : log1pf(expf(x));
}
__device__ __forceinline__ uint32_t tf32u(float x){
    uint32_t u;
    asm("cvt.rna.tf32.f32 %0, %1;" : "=r"(u) : "f"(x));
    return u;
}
__device__ __forceinline__ unsigned flipf(float s){
    unsigned u = __float_as_uint(s);
    return (u & 0x80000000u) ? ~u : (u | 0x80000000u);
}
__device__ __forceinline__ __half2 tanh2(__half2 x){
    uint32_t r, a = *(uint32_t*)&x;
    asm("tanh.approx.f16x2 %0, %1;" : "=r"(r) : "r"(a));
    return *(__half2*)&r;
}
__device__ __forceinline__ void cp16(uint32_t smem_addr, const void* gptr){
    asm volatile("cp.async.cg.shared.global [%0], [%1], 16;\n"
                 :: "r"(smem_addr), "l"(gptr));
}
__device__ __forceinline__ void cp_commit(){
    asm volatile("cp.async.commit_group;\n");
}
template <int N>
__device__ __forceinline__ void cp_wait(){
    asm volatile("cp.async.wait_group %0;\n" :: "n"(N));
}
__device__ __forceinline__ void mma_tf32(float* d, const uint32_t* a, const uint32_t* b){
    asm("mma.sync.aligned.m16n8k8.row.col.f32.tf32.tf32.f32 "
        "{%0,%1,%2,%3}, {%4,%5,%6,%7}, {%8,%9}, {%0,%1,%2,%3};"
        : "+f"(d[0]), "+f"(d[1]), "+f"(d[2]), "+f"(d[3])
        : "r"(a[0]), "r"(a[1]), "r"(a[2]), "r"(a[3]), "r"(b[0]), "r"(b[1]));
}
__device__ __forceinline__ void mma_f16(float* d, uint32_t a0, uint32_t a1, uint32_t a2,
                                        uint32_t a3, uint32_t b0, uint32_t b1){
    asm("mma.sync.aligned.m16n8k16.row.col.f32.f16.f16.f32 "
        "{%0,%1,%2,%3}, {%4,%5,%6,%7}, {%8,%9}, {%0,%1,%2,%3};"
        : "+f"(d[0]), "+f"(d[1]), "+f"(d[2]), "+f"(d[3])
        : "r"(a0), "r"(a1), "r"(a2), "r"(a3), "r"(b0), "r"(b1));
}
__device__ __forceinline__ unsigned long long warp_max_ull(unsigned long long v){
#pragma unroll
    for (int o = 16; o; o >>= 1) {
        unsigned long long w = __shfl_xor_sync(0xffffffffu, v, o);
        if (w > v) v = w;
    }
    return v;
}
__device__ __forceinline__ float warp_fmax(float v){
#pragma unroll
    for (int o = 16; o; o >>= 1)
        v = fmaxf(v, __shfl_xor_sync(0xffffffffu, v, o));
    return v;
}

// ---------------- tf32 GEMM, cp.async double-buffered -----------------------------
// C = A[MxK] @ W[KxN] + bias. tf32 rounding applied at fragment read (cvt.rna),
// numerically identical to rounding at store.
#define GEMM_SMEM (2*(128*36 + 32*72)*4)   // 55296 B
__global__ __launch_bounds__(256) void gemm32_kernel(
    const float* A, const float* W, const float* bias, float* C,
    int M, int N, int Kd, int aload, int smode,
    const float* A2, const float* W2, const float* bias2, float* C2, int halfM)
{
    extern __shared__ float smf[];
    float* As = smf;                 // [2][128][36]
    float* Bs = smf + 2*128*36;      // [2][32][72]
    int bm = blockIdx.y * 128;
    const int bn = blockIdx.x * 64;
    if (halfM && bm >= halfM) { A = A2; W = W2; bias = bias2; C = C2; bm -= halfM; }
    const int tid  = threadIdx.x;
    const int warp = tid >> 5, lane = tid & 31;
    const int wm = warp & 3, wn = warp >> 2;
    const int q = lane >> 2, c = lane & 3;

    // per-thread staging coordinates
    const int am = tid >> 3, akq = (tid & 7) * 4;     // A: 2 chunks of 128 rows? no: 4
    const int bk = tid >> 4, bnq = (tid & 15) * 4;

    float d[2][4][4];
#pragma unroll
    for (int mt = 0; mt < 2; mt++)
#pragma unroll
        for (int nt = 0; nt < 4; nt++)
#pragma unroll
            for (int i = 0; i < 4; i++) d[mt][nt][i] = 0.f;

    const int NIT = Kd / 32;

    // stage issuer
    auto issue = [&](int k0, int buf){
#pragma unroll
        for (int i = 0; i < 4; i++) {
            int id = tid + i * 256;
            int m = id >> 3, kq = (id & 7) * 4;
            const float* src;
            if (aload) {
                int mm = bm + m; int b = mm >> 11, l = mm & 2047;
                int k = k0 + kq; int h = k >> 6, hd = k & 63;
                src = &A[(((size_t)b * HH + h) * LL + l) * HD + hd];
            } else {
                src = &A[(size_t)(bm + m) * Kd + k0 + kq];
            }
            uint32_t dst = (uint32_t)__cvta_generic_to_shared(
                &As[((size_t)buf * 128 + m) * 36 + kq]);
            cp16(dst, src);
        }
#pragma unroll
        for (int i = 0; i < 2; i++) {
            int id = tid + i * 256;
            int kk = id >> 4, nq = (id & 15) * 4;
            const float* src = &W[(size_t)(k0 + kk) * N + bn + nq];
            uint32_t dst = (uint32_t)__cvta_generic_to_shared(
                &Bs[((size_t)buf * 32 + kk) * 72 + nq]);
            cp16(dst, src);
        }
        cp_commit();
    };

    issue(0, 0);
    for (int it = 0; it < NIT; it++) {
        int buf = it & 1;
        if (it + 1 < NIT) { issue((it + 1) * 32, buf ^ 1); cp_wait<1>(); }
        else              { cp_wait<0>(); }
        __syncthreads();
        const float* Ab = &As[(size_t)buf * 128 * 36];
        const float* Bb = &Bs[(size_t)buf * 32 * 72];
#pragma unroll
        for (int k8 = 0; k8 < 4; k8++) {
            uint32_t a[2][4], b[4][2];
#pragma unroll
            for (int mt = 0; mt < 2; mt++) {
                int r0 = wm * 32 + mt * 16 + q;
                a[mt][0] = tf32u(Ab[(size_t)r0 * 36 + k8 * 8 + c]);
                a[mt][1] = tf32u(Ab[(size_t)(r0 + 8) * 36 + k8 * 8 + c]);
                a[mt][2] = tf32u(Ab[(size_t)r0 * 36 + k8 * 8 + c + 4]);
                a[mt][3] = tf32u(Ab[(size_t)(r0 + 8) * 36 + k8 * 8 + c + 4]);
            }
#pragma unroll
            for (int nt = 0; nt < 4; nt++) {
                int cn = wn * 32 + nt * 8 + q;
                b[nt][0] = tf32u(Bb[(size_t)(k8 * 8 + c) * 72 + cn]);
                b[nt][1] = tf32u(Bb[(size_t)(k8 * 8 + c + 4) * 72 + cn]);
            }
#pragma unroll
            for (int mt = 0; mt < 2; mt++)
#pragma unroll
                for (int nt = 0; nt < 4; nt++)
                    mma_tf32(d[mt][nt], a[mt], b[nt]);
        }
        __syncthreads();
    }

#pragma unroll
    for (int mt = 0; mt < 2; mt++) {
        int gm0 = bm + wm * 32 + mt * 16 + q;
#pragma unroll
        for (int nt = 0; nt < 4; nt++) {
            int gn = bn + wn * 32 + nt * 8 + 2 * c;
            float b0 = __ldg(&bias[gn]), b1 = __ldg(&bias[gn + 1]);
            float v0 = d[mt][nt][0] + b0, v1 = d[mt][nt][1] + b1;
            float v2 = d[mt][nt][2] + b0, v3 = d[mt][nt][3] + b1;
            if (smode == 1) {
                int bb = gm0 >> 11, l = gm0 & 2047, h = gn >> 6, hd = gn & 63;
                float* p0 = &C[(((size_t)bb * HH + h) * LL + l) * HD + hd];
                p0[0] = v0; p0[1] = v1;
                float* p2 = &C[(((size_t)bb * HH + h) * LL + (l + 8)) * HD + hd];
                p2[0] = v2; p2[1] = v3;
            } else {
                *(float2*)&C[(size_t)gm0 * N + gn] = make_float2(v0, v1);
                *(float2*)&C[(size_t)(gm0 + 8) * N + gn] = make_float2(v2, v3);
            }
        }
    }
}

// ---------------- 512->48 projection (both inputs) + folded Wl2 prep --------------
// Register-prefetched: LDG of next k-tile overlaps compute. Blocks >= 256 do the
// Wl2 transpose+fp16 convert instead (prep fold).
__global__ __launch_bounds__(128) void proj_kernel(
    const float* __restrict__ Xt, const float* __restrict__ Xc,
    const float* __restrict__ W1, const float* __restrict__ W2, const float* __restrict__ W3,
    float* __restrict__ O1t, float* __restrict__ O2t, float* __restrict__ O3t,
    float* __restrict__ O1c, float* __restrict__ O2c, float* __restrict__ O3c,
    const float* __restrict__ Wl2)
{
    const int tid = threadIdx.x;
    if (blockIdx.x >= 256) {                     // prep path (32 blocks x 128)
        int n = (blockIdx.x - 256) * 128 + tid;
        if (n < NLAM) {
#pragma unroll
            for (int k = 0; k < EH; k++)
                g_Wl2h[n * EH + k] = __float2half(Wl2[(size_t)k * NLAM + n]);
        }
        return;
    }

    __shared__ float Xs[32][68];
    __shared__ float Ws[64][52];
    const int grow0 = blockIdx.x * 32;
    const int sel = grow0 >= (BB * LL);
    const float* X = sel ? Xc : Xt;
    const int row0 = grow0 & (BB * LL - 1);
    const int koff = sel ? DD : 0;
    const int r = tid >> 2, c0 = (tid & 3) * 12;

    float acc[12];
#pragma unroll
    for (int j = 0; j < 12; j++) acc[j] = 0.f;

    float4 rx[4], rw[2][3];
    // prefetch k0 = 0
    {
#pragma unroll
        for (int i = 0; i < 4; i++) {
            int id = tid + i * 128;
            int rr = id >> 4, qq = (id & 15) * 4;
            rx[i] = *(const float4*)&X[(size_t)(row0 + rr) * DD + qq];
        }
#pragma unroll
        for (int i = 0; i < 2; i++) {
            int id = tid + i * 128;
            int kr = id >> 2, qq = (id & 3) * 4;
            rw[i][0] = *(const float4*)&W1[(size_t)(koff + kr) * EH + qq];
            rw[i][1] = *(const float4*)&W2[(size_t)(koff + kr) * EH + qq];
            rw[i][2] = *(const float4*)&W3[(size_t)(koff + kr) * EH + qq];
        }
    }

    for (int k0 = 0; k0 < DD; k0 += 64) {
        // store staged regs
#pragma unroll
        for (int i = 0; i < 4; i++) {
            int id = tid + i * 128;
            int rr = id >> 4, qq = (id & 15) * 4;
            *(float4*)&Xs[rr][qq] = rx[i];
        }
#pragma unroll
        for (int i = 0; i < 2; i++) {
            int id = tid + i * 128;
            int kr = id >> 2, qq = (id & 3) * 4;
            *(float4*)&Ws[kr][ 0 + qq] = rw[i][0];
            *(float4*)&Ws[kr][16 + qq] = rw[i][1];
            *(float4*)&Ws[kr][32 + qq] = rw[i][2];
        }
        __syncthreads();
        // prefetch next tile (overlaps compute)
        int kn = k0 + 64;
        if (kn < DD) {
#pragma unroll
            for (int i = 0; i < 4; i++) {
                int id = tid + i * 128;
                int rr = id >> 4, qq = (id & 15) * 4;
                rx[i] = *(const float4*)&X[(size_t)(row0 + rr) * DD + kn + qq];
            }
#pragma unroll
            for (int i = 0; i < 2; i++) {
                int id = tid + i * 128;
                int kr = id >> 2, qq = (id & 3) * 4;
                rw[i][0] = *(const float4*)&W1[(size_t)(koff + kn + kr) * EH + qq];
                rw[i][1] = *(const float4*)&W2[(size_t)(koff + kn + kr) * EH + qq];
                rw[i][2] = *(const float4*)&W3[(size_t)(koff + kn + kr) * EH + qq];
            }
        }
#pragma unroll
        for (int k = 0; k < 64; k++) {
            float x = Xs[r][k];
            float4 w0 = *(const float4*)&Ws[k][c0];
            float4 w1 = *(const float4*)&Ws[k][c0 + 4];
            float4 w2 = *(const float4*)&Ws[k][c0 + 8];
            acc[0] += x * w0.x;  acc[1] += x * w0.y;  acc[2]  += x * w0.z;  acc[3]  += x * w0.w;
            acc[4] += x * w1.x;  acc[5] += x * w1.y;  acc[6]  += x * w1.z;  acc[7]  += x * w1.w;
            acc[8] += x * w2.x;  acc[9] += x * w2.y;  acc[10] += x * w2.z;  acc[11] += x * w2.w;
        }
        __syncthreads();
    }

    const int row = row0 + r;
#pragma unroll
    for (int j = 0; j < 12; j++) {
        int cc = c0 + j;
        int m = cc >> 4, col = cc & 15;
        float* O = sel ? (m == 0 ? O1c : m == 1 ? O2c : O3c)
                       : (m == 0 ? O1t : m == 1 ? O2t : O3t);
        O[(size_t)row * EH + col] = acc[j];
        if (sel && m == 0)
            g_SBh[(size_t)row * EH + col] = __float2half(acc[j]);
    }
}

// ---------------- score + top-8: tanh-gelu approx, float threshold, exact rescue ---
__global__ __launch_bounds__(256) void score_topk_kernel(
    const float* __restrict__ bs1, const float* __restrict__ Ws2, const float* __restrict__ bs2)
{
    __shared__ float a16[EH];
    __shared__ float w2s[EH];
    __shared__ __half2 a2h[8];
    __shared__ __half2 w2h[8];
    __shared__ float s_wv[8][8];
    __shared__ unsigned long long s_wk[8][8];
    __shared__ int s_surv[SCAP];
    __shared__ int s_cnt;
    __shared__ float s_thr;

    int b = blockIdx.x >> 11, l = blockIdx.x & 2047;
    int tid = threadIdx.x;
    int warp = tid >> 5, lane = tid & 31;
    if (tid < EH) {
        a16[tid] = g_SA[((size_t)b * LL + l) * EH + tid] + bs1[tid];
        w2s[tid] = Ws2[tid];
    }
    __syncthreads();
    if (tid < 8) {
        a2h[tid] = __floats2half2_rn(a16[2 * tid], a16[2 * tid + 1]);
        w2h[tid] = __floats2half2_rn(w2s[2 * tid], w2s[2 * tid + 1]);
    }
    __syncthreads();
    float aR[EH], wR[EH];
#pragma unroll
    for (int c = 0; c < EH; c++) { aR[c] = a16[c]; wR[c] = w2s[c]; }
    __half2 aH[8], wH[8];
#pragma unroll
    for (int c = 0; c < 8; c++) { aH[c] = a2h[c]; wH[c] = w2h[c]; }
    float bs2v = bs2[0];
    const __half2 C1 = __float2half2_rn(0.0356774081f);   // 0.79788456*0.044715
    const __half2 C0 = __float2half2_rn(0.7978845608f);
    const __half2 H5 = __float2half2_rn(0.5f);
    const float NINF = __int_as_float(0xff800000);

    // phase A: half2 tanh-gelu scores, per-thread fp32 max only (no keys)
    float s8[8];
    float tmax = NINF;
#pragma unroll
    for (int i = 0; i < 8; i++) {
        int kk = tid + i * 256;
        const uint4* bp = (const uint4*)(g_SBh + ((size_t)b * KK + kk) * EH);
        uint4 r0 = bp[0], r1 = bp[1];
        uint32_t bw[8] = {r0.x, r0.y, r0.z, r0.w, r1.x, r1.y, r1.z, r1.w};
        __half2 acc = __float2half2_rn(0.f);
#pragma unroll
        for (int c = 0; c < 8; c++) {
            __half2 h  = __hadd2(aH[c], *(__half2*)&bw[c]);
            __half2 p  = __hmul2(h, h);
            __half2 qq = __hfma2(p, C1, C0);
            __half2 t  = __hmul2(h, qq);
            __half2 th = tanh2(t);
            __half2 hh = __hmul2(h, H5);
            __half2 rs = __hfma2(hh, th, hh);
            acc = __hfma2(rs, wH[c], acc);
        }
        float2 f = __half22float2(acc);
        float s = f.x + f.y + bs2v;
        s8[i] = s;
        tmax = fmaxf(tmax, s);
    }

    // warp top-8 over 32 thread-maxes (fp32 fmax + shuffle)
    {
        float v = tmax;
#pragma unroll
        for (int p = 0; p < 8; p++) {
            float best = warp_fmax(v);
            if (v == best) v = NINF;
            if (lane == 0) s_wv[warp][p] = best;
        }
    }
    __syncthreads();

    // warp 0: merge 64 -> t8' and threshold
    if (warp == 0) {
        float va = ((float*)s_wv)[lane];
        float vb = ((float*)s_wv)[lane + 32];
        float t8 = NINF;
#pragma unroll
        for (int p = 0; p < 8; p++) {
            float m = fmaxf(va, vb);
            float best = warp_fmax(m);
            if (va == best) va = NINF; else if (vb == best) vb = NINF;
            t8 = best;
        }
        if (lane == 0) {
            float sw = 0.f;
#pragma unroll
            for (int c = 0; c < EH; c++) sw += fabsf(w2s[c]);
            s_thr = t8 - (sw * 0.03f + 0.06f);
            s_cnt = 0;
        }
    }
    __syncthreads();

    // survivor scan from register scores
    float thr = s_thr;
#pragma unroll
    for (int i = 0; i < 8; i++) {
        if (s8[i] >= thr) {
            int p = atomicAdd(&s_cnt, 1);
            if (p < SCAP) s_surv[p] = tid + i * 256;
        }
    }
    __syncthreads();
    int n = s_cnt;
    bool fb = (n > SCAP);

    unsigned long long key = 0ull;
    if (!fb) {
        if (tid < n) {
            int kk = s_surv[tid];
            const float4* bp = (const float4*)(g_SB + ((size_t)b * KK + kk) * EH);
            float4 b0 = bp[0], b1 = bp[1], b2 = bp[2], b3 = bp[3];
            float bv[EH] = {b0.x,b0.y,b0.z,b0.w, b1.x,b1.y,b1.z,b1.w,
                            b2.x,b2.y,b2.z,b2.w, b3.x,b3.y,b3.z,b3.w};
            float s = bs2v;
#pragma unroll
            for (int c = 0; c < EH; c++) s += geluf(aR[c] + bv[c]) * wR[c];
            key = (((unsigned long long)flipf(s)) << 32) | (unsigned)(KK - 1 - kk);
        }
#pragma unroll
        for (int p = 0; p < 8; p++) {
            unsigned long long best = warp_max_ull(key);
            if (key == best && best != 0ull) key = 0ull;
            if (lane == 0) s_wk[warp][p] = best;
        }
    } else {
        // fallback: exact rescore of everything (rare)
        unsigned long long k8[8];
#pragma unroll
        for (int i = 0; i < 8; i++) {
            int kk = tid + i * 256;
            const float4* bp = (const float4*)(g_SB + ((size_t)b * KK + kk) * EH);
            float4 b0 = bp[0], b1 = bp[1], b2 = bp[2], b3 = bp[3];
            float bv[EH] = {b0.x,b0.y,b0.z,b0.w, b1.x,b1.y,b1.z,b1.w,
                            b2.x,b2.y,b2.z,b2.w, b3.x,b3.y,b3.z,b3.w};
            float s = bs2v;
#pragma unroll
            for (int c = 0; c < EH; c++) s += geluf(aR[c] + bv[c]) * wR[c];
            k8[i] = (((unsigned long long)flipf(s)) << 32) | (unsigned)(KK - 1 - kk);
        }
        unsigned long long lm = k8[0]; int am = 0;
#pragma unroll
        for (int i = 1; i < 8; i++) if (k8[i] > lm) { lm = k8[i]; am = i; }
#pragma unroll
        for (int p = 0; p < 8; p++) {
            unsigned long long best = warp_max_ull(lm);
            if (lm == best && best != 0ull) {
                k8[am] = 0ull;
                lm = k8[0]; am = 0;
#pragma unroll
                for (int i = 1; i < 8; i++) if (k8[i] > lm) { lm = k8[i]; am = i; }
            }
            if (lane == 0) s_wk[warp][p] = best;
        }
    }
    __syncthreads();

    if (warp == 0) {
        unsigned long long ka = ((unsigned long long*)s_wk)[lane];
        unsigned long long kb = ((unsigned long long*)s_wk)[lane + 32];
#pragma unroll
        for (int p = 0; p < 8; p++) {
            unsigned long long m = ka > kb ? ka : kb;
            unsigned long long best = warp_max_ull(m);
            if (ka == best) ka = 0ull; else if (kb == best) kb = 0ull;
            if (lane == 0)
                g_idx[((size_t)b * LL + l) * WWIN + p] = KK - 1 - (int)(best & 0xffffffffu);
        }
    }
}

// ---------------- fused consensus: gh/alpha + in-block Lam MMA + T=2 iterations ---
#define ITER_DYN_SMEM (8*LAMP*2 + 8*HH*HD*4)   // 65792 + 16384 = 82176 B
__global__ __launch_bounds__(256) void iter2_kernel(
    const float* __restrict__ step_sizes, const float* __restrict__ bl1,
    const float* __restrict__ ba1, const float* __restrict__ Wa2,
    const float* __restrict__ ba2, const float* __restrict__ bl2)
{
    extern __shared__ char dyn[];
    __half* s_lam = (__half*)dyn;                        // [8e] x LAMP halves
    float*  s_v   = (float*)(dyn + 8*LAMP*2);            // [8e][H][64]
    __shared__ float s_cs[8][32];
    __shared__ float s_sn[8][32];
    __shared__ float s_alpha[8];
    __shared__ int   s_idx[8];
    __shared__ __half s_gh[8][EH];

    int b = blockIdx.x >> 11, l = blockIdx.x & 2047;
    int tid = threadIdx.x;
    int wi = tid >> 5, ln = tid & 31;
    int eg = ln >> 3, dg = ln & 7;
    int q = ln >> 2, cq = ln & 3;

    // per-edge small params: warp e owns edge e
    {
        int e = wi;
        int j = g_idx[((size_t)b * LL + l) * WWIN + e];
        if (ln == 0) s_idx[e] = j;
        float hav = 0.f;
        if (ln < EH) {
            int c = ln;
            float hl = g_LA[((size_t)b * LL + l) * EH + c]
                     + g_LB[((size_t)b * KK + j) * EH + c] + bl1[c];
            s_gh[e][c] = __float2half(geluf(hl));
            float ha = g_AA[((size_t)b * LL + l) * EH + c]
                     + g_AB[((size_t)b * KK + j) * EH + c] + ba1[c];
            hav = geluf(ha) * Wa2[c];
        }
#pragma unroll
        for (int o = 16; o; o >>= 1) hav += __shfl_xor_sync(0xffffffffu, hav, o);
        if (ln == 0) s_alpha[e] = softplusf(hav + ba2[0]);
        float ang = (float)(l - j) * exp2f((float)ln * -0.41524101186092029f);
        s_cs[e][ln] = cosf(ang);
        s_sn[e][ln] = sinf(ang);
    }
    __syncthreads();

    // stage gathered v rows
#pragma unroll
    for (int i = 0; i < 16; i++) {
        int gid = tid + i * 256;
        int e2 = gid >> 9, h2 = (gid >> 6) & 7, d = gid & 63;
        s_v[gid] = g_v[(((size_t)b * HH + h2) * KK + s_idx[e2]) * HD + d];
    }

    // generate Lam for head wi: rows = edges (A rows 0-7 valid), 512 cols per warp
    {
        uint32_t A0 = *(const uint32_t*)&s_gh[q][2 * cq];
        uint32_t A2 = *(const uint32_t*)&s_gh[q][2 * cq + 8];
        uint32_t Z = 0u;
#pragma unroll
        for (int rr = 0; rr < 8; rr++) {
            float v0a[8], v1a[8];
            float ssq = 0.f;
#pragma unroll
            for (int ii = 0; ii < 8; ii++) {
                int colq = wi * 512 + (rr * 8 + ii) * 8 + q;       // B col this thread
                const uint32_t* bp = (const uint32_t*)(g_Wl2h + (size_t)colq * EH);
                uint32_t b0 = bp[cq], b1 = bp[cq + 4];
                float dd[4] = {0.f, 0.f, 0.f, 0.f};
                mma_f16(dd, A0, Z, A2, Z, b0, b1);
                int ncol = wi * 512 + (rr * 8 + ii) * 8 + 2 * cq;  // output cols (edge q)
                float2 bb = *(const float2*)&bl2[ncol];
                v0a[ii] = dd[0] + bb.x;
                v1a[ii] = dd[1] + bb.y;
                ssq += v0a[ii] * v0a[ii] + v1a[ii] * v1a[ii];
            }
            ssq += __shfl_xor_sync(0xffffffffu, ssq, 1);
            ssq += __shfl_xor_sync(0xffffffffu, ssq, 2);
            float sc = 1.f / fmaxf(sqrtf(ssq), 1e-12f);
#pragma unroll
            for (int ii = 0; ii < 8; ii++) {
                int ncol = wi * 512 + (rr * 8 + ii) * 8 + 2 * cq;
                *(__half2*)&s_lam[(size_t)q * LAMP + ncol] =
                    __floats2half2_rn(v0a[ii] * sc, v1a[ii] * sc);
            }
        }
    }
    __syncthreads();

    size_t ubase = (((size_t)b * HH + wi) * LL + l) * HD;
    float4 u_lo = *(const float4*)&g_u[ubase + dg * 4];
    float4 u_hi = *(const float4*)&g_u[ubase + 32 + dg * 4];

#pragma unroll
    for (int t = 0; t < TT; t++) {
        float stp = softplusf(step_sizes[t * LL + l]);
        float al4[4] = {0.f,0.f,0.f,0.f}, ah4[4] = {0.f,0.f,0.f,0.f};
#pragma unroll
        for (int eb = 0; eb < 2; eb++) {
            int e = eb * 4 + eg;
            float4 cs4 = *(const float4*)&s_cs[e][dg * 4];
            float4 sn4 = *(const float4*)&s_sn[e][dg * 4];
            const float4* vp = (const float4*)&s_v[(e * HH + wi) * HD + dg * 4];
            float4 vlo = vp[0], vhi = vp[8];
            float dlo[4], dhi[4];
            dlo[0] = u_lo.x * cs4.x - u_hi.x * sn4.x - vlo.x;
            dlo[1] = u_lo.y * cs4.y - u_hi.y * sn4.y - vlo.y;
            dlo[2] = u_lo.z * cs4.z - u_hi.z * sn4.z - vlo.z;
            dlo[3] = u_lo.w * cs4.w - u_hi.w * sn4.w - vlo.w;
            dhi[0] = u_hi.x * cs4.x + u_lo.x * sn4.x - vhi.x;
            dhi[1] = u_hi.y * cs4.y + u_lo.y * sn4.y - vhi.y;
            dhi[2] = u_hi.z * cs4.z + u_lo.z * sn4.z - vhi.z;
            dhi[3] = u_hi.w * cs4.w + u_lo.w * sn4.w - vhi.w;
            float alp = s_alpha[e];
            float rl[4] = {0.f,0.f,0.f,0.f}, rh[4] = {0.f,0.f,0.f,0.f};
            const __half2* lp = (const __half2*)(s_lam + (size_t)e * LAMP + wi * RR * HD);
#pragma unroll
            for (int rc = 0; rc < 2; rc++) {
                float2 F0[4], F1[4], F2[4], F3[4];
                float p4[4];
#pragma unroll
                for (int rr2 = 0; rr2 < 4; rr2++) {
                    int r = rc * 4 + rr2;
                    uint2 wlo = *(const uint2*)&lp[r * 32 + dg * 2];
                    uint2 whi = *(const uint2*)&lp[r * 32 + 16 + dg * 2];
                    F0[rr2] = __half22float2(*(__half2*)&wlo.x);
                    F1[rr2] = __half22float2(*(__half2*)&wlo.y);
                    F2[rr2] = __half22float2(*(__half2*)&whi.x);
                    F3[rr2] = __half22float2(*(__half2*)&whi.y);
                    p4[rr2] = F0[rr2].x * dlo[0] + F0[rr2].y * dlo[1]
                            + F1[rr2].x * dlo[2] + F1[rr2].y * dlo[3]
                            + F2[rr2].x * dhi[0] + F2[rr2].y * dhi[1]
                            + F3[rr2].x * dhi[2] + F3[rr2].y * dhi[3];
                }
#pragma unroll
                for (int o = 1; o <= 4; o <<= 1) {
#pragma unroll
                    for (int rr2 = 0; rr2 < 4; rr2++)
                        p4[rr2] += __shfl_xor_sync(0xffffffffu, p4[rr2], o);
                }
#pragma unroll
                for (int rr2 = 0; rr2 < 4; rr2++) {
                    rl[0] += p4[rr2] * F0[rr2].x; rl[1] += p4[rr2] * F0[rr2].y;
                    rl[2] += p4[rr2] * F1[rr2].x; rl[3] += p4[rr2] * F1[rr2].y;
                    rh[0] += p4[rr2] * F2[rr2].x; rh[1] += p4[rr2] * F2[rr2].y;
                    rh[2] += p4[rr2] * F3[rr2].x; rh[3] += p4[rr2] * F3[rr2].y;
                }
            }
#pragma unroll
            for (int i = 0; i < 4; i++) {
                al4[i] += alp * dlo[i] + rl[i];
                ah4[i] += alp * dhi[i] + rh[i];
            }
        }
#pragma unroll
        for (int i = 0; i < 4; i++) {
            al4[i] += __shfl_xor_sync(0xffffffffu, al4[i], 8);
            al4[i] += __shfl_xor_sync(0xffffffffu, al4[i], 16);
            ah4[i] += __shfl_xor_sync(0xffffffffu, ah4[i], 8);
            ah4[i] += __shfl_xor_sync(0xffffffffu, ah4[i], 16);
        }
        u_lo.x -= stp * al4[0]; u_lo.y -= stp * al4[1];
        u_lo.z -= stp * al4[2]; u_lo.w -= stp * al4[3];
        u_hi.x -= stp * ah4[0]; u_hi.y -= stp * ah4[1];
        u_hi.z -= stp * ah4[2]; u_hi.w -= stp * ah4[3];
    }
    if (eg == 0) {
        *(float4*)&g_u[ubase + dg * 4] = u_lo;
        *(float4*)&g_u[ubase + 32 + dg * 4] = u_hi;
    }
}

// ---------------- launch ----------------
extern "C" void kernel_launch(void* const* d_in, const int* in_sizes, int n_in,
                              void* d_out, int out_size)
{
    const float* target = (const float*)d_in[0];
    const float* context= (const float*)d_in[1];
    const float* Wt  = (const float*)d_in[2];
    const float* bt  = (const float*)d_in[3];
    const float* Wc  = (const float*)d_in[4];
    const float* bc  = (const float*)d_in[5];
    const float* Ws1 = (const float*)d_in[6];
    const float* bs1 = (const float*)d_in[7];
    const float* Ws2 = (const float*)d_in[8];
    const float* bs2 = (const float*)d_in[9];
    const float* Wa1 = (const float*)d_in[10];
    const float* ba1 = (const float*)d_in[11];
    const float* Wa2 = (const float*)d_in[12];
    const float* ba2 = (const float*)d_in[13];
    const float* Wl1 = (const float*)d_in[14];
    const float* bl1 = (const float*)d_in[15];
    const float* Wl2 = (const float*)d_in[16];
    const float* bl2 = (const float*)d_in[17];
    const float* step_sizes = (const float*)d_in[18];
    const float* Wo  = (const float*)d_in[19];
    const float* bo  = (const float*)d_in[20];

    float *pu, *pv, *pSA, *pSB, *pAA, *pAB, *pLA, *pLB;
    cudaGetSymbolAddress((void**)&pu,  g_u);
    cudaGetSymbolAddress((void**)&pv,  g_v);
    cudaGetSymbolAddress((void**)&pSA, g_SA);
    cudaGetSymbolAddress((void**)&pSB, g_SB);
    cudaGetSymbolAddress((void**)&pAA, g_AA);
    cudaGetSymbolAddress((void**)&pAB, g_AB);
    cudaGetSymbolAddress((void**)&pLA, g_LA);
    cudaGetSymbolAddress((void**)&pLB, g_LB);

    cudaFuncSetAttribute(iter2_kernel, cudaFuncAttributeMaxDynamicSharedMemorySize,
                         ITER_DYN_SMEM);
    cudaFuncSetAttribute(gemm32_kernel, cudaFuncAttributeMaxDynamicSharedMemorySize,
                         GEMM_SMEM);

    const int Mrows = BB * LL;  // 4096

    // u and v projections in one launch (cp.async double-buffered)
    gemm32_kernel<<<dim3(DD/64, (2*Mrows)/128), 256, GEMM_SMEM>>>(
        target, Wt, bt, pu, 2*Mrows, DD, DD, 0, 1, context, Wc, bc, pv, Mrows);

    // separable 16-dim projections + folded Wl2 prep (grid 256 + 32)
    proj_kernel<<<288, 128>>>(target, context, Ws1, Wa1, Wl1,
                              pSA, pAA, pLA, pSB, pAB, pLB, Wl2);

    // scores + top-8 (tanh-gelu approx, float threshold, exact rescue)
    score_topk_kernel<<<BB * LL, 256>>>(bs1, Ws2, bs2);

    // fused: edge params + in-block Lam generation + both consensus iterations
    iter2_kernel<<<BB * LL, 256, ITER_DYN_SMEM>>>(step_sizes, bl1, ba1, Wa2, ba2, bl2);

    gemm32_kernel<<<dim3(DD/64, Mrows/128), 256, GEMM_SMEM>>>(
        pu, Wo, bo, (float*)d_out, Mrows, DD, DD, 1, 0,
        nullptr, nullptr, nullptr, nullptr, 0);
}